// round 2
// baseline (speedup 1.0000x reference)
#include <cuda_runtime.h>
#include <math.h>

// Problem constants
#define Bsz   1024
#define Tlen  128
#define Hdim  512
#define G4    2048      // 4*H
#define NCLS  10

// Tiling
#define BM 128          // rows per block
#define BN 32           // within-gate cols per block (x4 gates = 128 W rows)
#define KT 16           // K tile

// Persistent device state (allocation-free scratch)
__device__ float g_h[2][Bsz * Hdim];
__device__ float g_c[Bsz * Hdim];
__device__ float g_gx[3][G4];

// ---------- packed f32x2 helpers (sm_103a) ----------
__device__ __forceinline__ unsigned long long pk2(float lo, float hi) {
    unsigned long long r;
    asm("mov.b64 %0, {%1,%2};" : "=l"(r) : "f"(lo), "f"(hi));
    return r;
}
__device__ __forceinline__ void fma2(unsigned long long& d, unsigned long long a, unsigned long long b) {
    asm("fma.rn.f32x2 %0, %1, %2, %0;" : "+l"(d) : "l"(a), "l"(b));
}
__device__ __forceinline__ float2 upk2(unsigned long long v) {
    float2 r;
    asm("mov.b64 {%0,%1}, %2;" : "=f"(r.x), "=f"(r.y) : "l"(v));
    return r;
}

__device__ __forceinline__ float sigmoidf_(float x) { return 1.0f / (1.0f + expf(-x)); }

// ---------- prologue: zero state + build gx table ----------
__global__ void lstm_init(const float* __restrict__ emb,
                          const float* __restrict__ Wx,
                          const float* __restrict__ bias) {
    int i = blockIdx.x * blockDim.x + threadIdx.x;
    if (i < Bsz * Hdim) {
        g_h[0][i] = 0.0f;
        g_c[i]    = 0.0f;
    }
    if (i < 3 * G4) {
        int d = i >> 11;        // /2048
        int j = i & (G4 - 1);
        g_gx[d][j] = bias[j] + Wx[j * 2 + 0] * emb[d * 2 + 0]
                             + Wx[j * 2 + 1] * emb[d * 2 + 1];
    }
}

// ---------- one recurrent step: z = gx + h @ Wh^T, fused gates + state update ----------
__global__ __launch_bounds__(256, 1)
void lstm_step(const int* __restrict__ x, const float* __restrict__ Wh, int t) {
    __shared__ float sh_h[2][KT][BM];        // [buf][k][row]
    __shared__ float sh_w[2][KT][4 * BN];    // [buf][k][c], c = gate*32 + within-gate col
    __shared__ float sh_gx[3][4 * BN];

    const int tid = threadIdx.x;
    const int tx = tid & 15;     // 0..15 -> 2 within-gate cols each
    const int ty = tid >> 4;     // 0..15 -> 8 rows each
    const int m0 = blockIdx.y * BM;
    const int n0 = blockIdx.x * BN;   // within-gate column offset

    const float* __restrict__ hin  = g_h[t & 1];
    float*       __restrict__ hout = g_h[(t + 1) & 1];

    // gx slice for this block's 128 combined columns (384 entries, 256 threads:
    // MUST stride — the round-1 bug was `if (tid < 384)` with blockDim 256,
    // leaving sh_gx[2][*] uninitialized)
    for (int i = tid; i < 3 * 128; i += 256) {
        int d = i >> 7;            // 0..2
        int c = i & 127;
        int j = (c >> 5) * Hdim + n0 + (c & 31);
        sh_gx[d][c] = g_gx[d][j];
    }

    // accumulators: [gate][col-in-pair][row-pair] as packed f32x2
    unsigned long long acc[4][2][4];
#pragma unroll
    for (int g = 0; g < 4; ++g)
#pragma unroll
        for (int cc = 0; cc < 2; ++cc)
#pragma unroll
            for (int p = 0; p < 4; ++p) acc[g][cc][p] = 0ull;

    // K loop with double-buffered shared tiles
    auto load_tile = [&](int kt, int bfb) {
#pragma unroll
        for (int r = 0; r < 2; ++r) {
            int f   = tid + r * 256;        // 0..511
            int row = f >> 2;               // 0..127
            int kq  = (f & 3) << 2;         // 0,4,8,12
            float4 hv = *(const float4*)&hin[(m0 + row) * Hdim + kt + kq];
            sh_h[bfb][kq + 0][row] = hv.x;
            sh_h[bfb][kq + 1][row] = hv.y;
            sh_h[bfb][kq + 2][row] = hv.z;
            sh_h[bfb][kq + 3][row] = hv.w;
            int j = (row >> 5) * Hdim + n0 + (row & 31);
            float4 wv = *(const float4*)&Wh[j * Hdim + kt + kq];
            sh_w[bfb][kq + 0][row] = wv.x;
            sh_w[bfb][kq + 1][row] = wv.y;
            sh_w[bfb][kq + 2][row] = wv.z;
            sh_w[bfb][kq + 3][row] = wv.w;
        }
    };

    load_tile(0, 0);
    __syncthreads();

#pragma unroll 1
    for (int kt = 0; kt < Hdim; kt += KT) {
        int buf = (kt >> 4) & 1;
        if (kt + KT < Hdim) load_tile(kt + KT, buf ^ 1);

#pragma unroll
        for (int k = 0; k < KT; ++k) {
            ulonglong2 hA = *(const ulonglong2*)&sh_h[buf][k][ty * 8];
            ulonglong2 hB = *(const ulonglong2*)&sh_h[buf][k][ty * 8 + 4];
            unsigned long long h2[4] = { hA.x, hA.y, hB.x, hB.y };
#pragma unroll
            for (int g = 0; g < 4; ++g) {
                float2 w = *(const float2*)&sh_w[buf][k][g * BN + 2 * tx];
                unsigned long long w0 = pk2(w.x, w.x);
                unsigned long long w1 = pk2(w.y, w.y);
#pragma unroll
                for (int p = 0; p < 4; ++p) {
                    fma2(acc[g][0][p], h2[p], w0);
                    fma2(acc[g][1][p], h2[p], w1);
                }
            }
        }
        __syncthreads();
    }

    // fused gate epilogue + state update
#pragma unroll
    for (int p = 0; p < 4; ++p) {
        float2 zv[4][2];
#pragma unroll
        for (int g = 0; g < 4; ++g) {
            zv[g][0] = upk2(acc[g][0][p]);
            zv[g][1] = upk2(acc[g][1][p]);
        }
#pragma unroll
        for (int s = 0; s < 2; ++s) {
            int b = m0 + ty * 8 + 2 * p + s;
            int d = x[b * Tlen + t];
            int idx = b * Hdim + n0 + 2 * tx;
            float2 cold = *(const float2*)&g_c[idx];
            float2 cn, hn;
#pragma unroll
            for (int cc = 0; cc < 2; ++cc) {
                int wc = 2 * tx + cc;
                float zg = (s ? zv[0][cc].y : zv[0][cc].x) + sh_gx[d][0 * BN + wc];
                float zi = (s ? zv[1][cc].y : zv[1][cc].x) + sh_gx[d][1 * BN + wc];
                float zf = (s ? zv[2][cc].y : zv[2][cc].x) + sh_gx[d][2 * BN + wc];
                float zo = (s ? zv[3][cc].y : zv[3][cc].x) + sh_gx[d][3 * BN + wc];
                float gg = tanhf(zg);
                float ii = sigmoidf_(zi);
                float ff = sigmoidf_(zf);
                float oo = sigmoidf_(zo);
                float cold_s = cc ? cold.y : cold.x;
                float cnew = gg * ii + cold_s * ff;
                float hnew = tanhf(cnew) * oo;
                if (cc) { cn.y = cnew; hn.y = hnew; }
                else    { cn.x = cnew; hn.x = hnew; }
            }
            *(float2*)&g_c[idx] = cn;
            *(float2*)&hout[idx] = hn;
        }
    }
}

// ---------- head: p = h @ Wp + bp; log_softmax. One warp per row. ----------
__global__ void lstm_head(const float* __restrict__ Wp,
                          const float* __restrict__ bp,
                          float* __restrict__ out) {
    int warp = threadIdx.x >> 5;
    int lane = threadIdx.x & 31;
    int row = blockIdx.x * 8 + warp;
    if (row >= Bsz) return;

    const float* __restrict__ h = &g_h[0][row * Hdim];   // T=128 even -> final h in buffer 0
    float acc[NCLS];
#pragma unroll
    for (int n = 0; n < NCLS; ++n) acc[n] = 0.0f;

    for (int k = lane; k < Hdim; k += 32) {
        float hv = h[k];
#pragma unroll
        for (int n = 0; n < NCLS; ++n) acc[n] += hv * Wp[k * NCLS + n];
    }
#pragma unroll
    for (int off = 16; off > 0; off >>= 1)
#pragma unroll
        for (int n = 0; n < NCLS; ++n)
            acc[n] += __shfl_xor_sync(0xFFFFFFFFu, acc[n], off);

    if (lane == 0) {
        float p[NCLS];
        float m = -1e30f;
#pragma unroll
        for (int n = 0; n < NCLS; ++n) {
            p[n] = acc[n] + bp[n];
            m = fmaxf(m, p[n]);
        }
        float ssum = 0.0f;
#pragma unroll
        for (int n = 0; n < NCLS; ++n) ssum += expf(p[n] - m);
        float lse = m + logf(ssum);
#pragma unroll
        for (int n = 0; n < NCLS; ++n) out[row * NCLS + n] = p[n] - lse;
    }
}

extern "C" void kernel_launch(void* const* d_in, const int* in_sizes, int n_in,
                              void* d_out, int out_size) {
    const int*   x   = (const int*)  d_in[0];   // (B, T) int32
    const float* emb = (const float*)d_in[1];   // (3, 2)
    const float* Wx  = (const float*)d_in[2];   // (4H, 2)
    const float* Wh  = (const float*)d_in[3];   // (4H, H)
    const float* b   = (const float*)d_in[4];   // (4H,)
    const float* Wp  = (const float*)d_in[5];   // (H, NCLS)
    const float* bp  = (const float*)d_in[6];   // (NCLS,)
    float* out = (float*)d_out;                 // (B, NCLS)

    lstm_init<<<1024, 512>>>(emb, Wx, b);

    dim3 grid(Hdim / BN, Bsz / BM);  // (16, 8) = 128 blocks
    for (int t = 0; t < Tlen; ++t)
        lstm_step<<<grid, 256>>>(x, Wh, t);

    lstm_head<<<Bsz / 8, 256>>>(Wp, bp, out);
}

// round 4
// speedup vs baseline: 1.1547x; 1.1547x over previous
#include <cuda_runtime.h>
#include <cuda_bf16.h>
#include <math.h>

// ---------------- problem constants ----------------
#define Bsz   1024
#define Tlen  128
#define Hdim  512
#define NCLS  10

// ---------------- tiling ----------------
#define MT 8            // M tiles (1024/128)
#define NT 16           // N tiles (2048/128) in permuted gate space
#define CH 8            // K chunks (512/64)
#define SLAB 16384      // 128 rows x 64 cols x 2B, SW128 slab

// ---------------- persistent device state (pre-swizzled) ----------------
__device__ __align__(16) unsigned char g_Wsw[2][NT][CH][SLAB];      // [prec][ntile][chunk] 4MB
__device__ __align__(16) unsigned char g_hsw[2][2][MT][CH][SLAB];   // [parity][prec][mtile][chunk] 4MB
__device__ float g_c[Bsz * Hdim];
__device__ float g_hfin[Bsz * Hdim];
__device__ float g_gxp[3][2048];     // permuted gate-bias table

// ---------------- PTX helpers (sm_103 plain — NO tcgen05) ----------------
__device__ __forceinline__ unsigned smem_u32(const void* p) {
    unsigned r;
    asm("{ .reg .u64 t; cvta.to.shared.u64 t, %1; cvt.u32.u64 %0, t; }" : "=r"(r) : "l"(p));
    return r;
}
__device__ __forceinline__ void bulk_g2s(unsigned dst, const void* src, unsigned bytes, unsigned mbar) {
    asm volatile("cp.async.bulk.shared::cluster.global.mbarrier::complete_tx::bytes [%0], [%1], %2, [%3];"
        :: "r"(dst), "l"(src), "r"(bytes), "r"(mbar) : "memory");
}
#define MBINIT(a, c)  asm volatile("mbarrier.init.shared.b64 [%0], %1;" :: "r"(a), "r"(c) : "memory")
#define MBEXPECT(a, n) asm volatile("mbarrier.arrive.expect_tx.shared.b64 _, [%0], %1;" :: "r"(a), "r"(n) : "memory")
#define MBARRIVE(a)   asm volatile("mbarrier.arrive.shared.b64 _, [%0];" :: "r"(a) : "memory")
#define FENCE_ASYNC() asm volatile("fence.proxy.async.shared::cta;" ::: "memory")

#define MBWAIT(mbar, parity) do {                                            \
    unsigned _m = (mbar); unsigned _p = (parity); unsigned _done;            \
    asm volatile("{\n\t.reg .pred p;\n\t"                                    \
        "mbarrier.try_wait.parity.acquire.cta.shared::cta.b64 p, [%1], %2;\n\t" \
        "selp.b32 %0, 1, 0, p;\n\t}"                                         \
        : "=r"(_done) : "r"(_m), "r"(_p) : "memory");                        \
    if (!_done) {                                                            \
        asm volatile("{\n\t.reg .pred P1;\n\t"                               \
            "WL_%=:\n\t"                                                     \
            "mbarrier.try_wait.parity.acquire.cta.shared::cta.b64 P1, [%0], %1, 0x989680;\n\t" \
            "@P1 bra.uni WD_%=;\n\t"                                         \
            "bra.uni WL_%=;\n\t"                                             \
            "WD_%=:\n\t}"                                                    \
            :: "r"(_m), "r"(_p) : "memory");                                 \
    }                                                                        \
} while (0)

__device__ __forceinline__ void ldsm4(unsigned* r, unsigned addr) {
    asm volatile("ldmatrix.sync.aligned.m8n8.x4.shared.b16 {%0,%1,%2,%3}, [%4];"
        : "=r"(r[0]), "=r"(r[1]), "=r"(r[2]), "=r"(r[3]) : "r"(addr));
}
__device__ __forceinline__ void mma_bf16(float* d, const unsigned* a, unsigned b0, unsigned b1) {
    asm volatile("mma.sync.aligned.m16n8k16.row.col.f32.bf16.bf16.f32 "
        "{%0,%1,%2,%3}, {%4,%5,%6,%7}, {%8,%9}, {%0,%1,%2,%3};"
        : "+f"(d[0]), "+f"(d[1]), "+f"(d[2]), "+f"(d[3])
        : "r"(a[0]), "r"(a[1]), "r"(a[2]), "r"(a[3]), "r"(b0), "r"(b1));
}

__device__ __forceinline__ unsigned sw128(unsigned o) { return o ^ ((o >> 3) & 0x70); }
__device__ __forceinline__ float sigf(float x) { return __fdividef(1.0f, 1.0f + __expf(-x)); }
__device__ __forceinline__ float tanh_fast(float x) {
    float a = fabsf(x);
    float e = __expf(2.0f * a);
    float r = 1.0f - __fdividef(2.0f, e + 1.0f);   // inf-safe
    return copysignf(r, x);
}

// ---------------- init: zero state, build permuted+swizzled Wh hi/lo + gx table ----------------
__global__ void lstm_init(const float* __restrict__ emb,
                          const float* __restrict__ Wx,
                          const float* __restrict__ bias,
                          const float* __restrict__ Wh) {
    int i = blockIdx.x * blockDim.x + threadIdx.x;   // 0 .. 1M-1

    // Wsw: permuted c = hcol*4 + gate
    {
        int c = i >> 9;              // 0..2047
        int k = i & 511;
        int r = (c & 3) * Hdim + (c >> 2);
        float w = Wh[r * Hdim + k];
        __nv_bfloat16 hi = __float2bfloat16(w);
        __nv_bfloat16 lo = __float2bfloat16(w - __bfloat162float(hi));
        int ntile = c >> 7, rl = c & 127, chunk = k >> 6, col = k & 63;
        unsigned byte = (unsigned)((rl >> 3) * 1024 + (rl & 7) * 128 + col * 2);
        unsigned so = sw128(byte);
        *(__nv_bfloat16*)(g_Wsw[0][ntile][chunk] + so) = hi;
        *(__nv_bfloat16*)(g_Wsw[1][ntile][chunk] + so) = lo;
    }
    // zero h parity-0 slabs (both precisions): 2MB = 512K words
    if (i < 524288) ((unsigned*)g_hsw[0])[i] = 0u;
    // zero c
    if (i < Bsz * Hdim) g_c[i] = 0.0f;
    // gx table (permuted)
    if (i < 3 * 2048) {
        int d = i >> 11, c = i & 2047;
        int r = (c & 3) * Hdim + (c >> 2);
        g_gxp[d][c] = bias[r] + Wx[r * 2 + 0] * emb[d * 2 + 0]
                              + Wx[r * 2 + 1] * emb[d * 2 + 1];
    }
}

// ---------------- one LSTM step: mma.sync bf16 hi/lo, fused epilogue ----------------
#define SM_FULL0  0
#define SM_EMPTY0 16
#define SM_GX     64
#define SM_SLABS  2048
#define BUFBYTES  65536
#define SMEM_TOTAL (SM_SLABS + 2 * BUFBYTES)

__global__ __launch_bounds__(288, 1)
void lstm_step_mma(const int* __restrict__ x, int t) {
    extern __shared__ char smem[];
    const unsigned sbase = smem_u32(smem);
    const int tid = threadIdx.x;
    const int nt = blockIdx.x, mt = blockIdx.y;
    const int m0 = mt * 128, n0 = nt * 128;
    const int par = t & 1, np = par ^ 1;

    float* sh_gx = (float*)(smem + SM_GX);
    if (tid < 256) {
        for (int i = tid; i < 384; i += 256) {
            int d = i >> 7, c = i & 127;
            sh_gx[d * 128 + c] = g_gxp[d][n0 + c];
        }
    }

    unsigned full[2] = { sbase + SM_FULL0,  sbase + SM_FULL0 + 8 };
    unsigned empt[2] = { sbase + SM_EMPTY0, sbase + SM_EMPTY0 + 8 };
    if (tid == 256) {
        MBINIT(full[0], 1);   MBINIT(full[1], 1);
        MBINIT(empt[0], 256); MBINIT(empt[1], 256);
        FENCE_ASYNC();
    }
    __syncthreads();

    if (tid >= 256) {
        // -------- producer warp (only lane 0 acts) --------
        if (tid == 256) {
            auto load_chunk = [&](int chunk, int buf) {
                unsigned d0 = sbase + SM_SLABS + buf * BUFBYTES;
                MBEXPECT(full[buf], 4 * SLAB);
                bulk_g2s(d0,            g_hsw[par][0][mt][chunk], SLAB, full[buf]);  // A hi
                bulk_g2s(d0 + SLAB,     g_hsw[par][1][mt][chunk], SLAB, full[buf]);  // A lo
                bulk_g2s(d0 + 2 * SLAB, g_Wsw[0][nt][chunk],      SLAB, full[buf]);  // B hi
                bulk_g2s(d0 + 3 * SLAB, g_Wsw[1][nt][chunk],      SLAB, full[buf]);  // B lo
            };
            load_chunk(0, 0);
            load_chunk(1, 1);
            int phe[2] = { 0, 0 };
            for (int c = 0; c + 2 < CH; ++c) {
                int buf = c & 1;
                MBWAIT(empt[buf], phe[buf]); phe[buf] ^= 1;
                load_chunk(c + 2, buf);
            }
        }
        return;
    }

    // -------- compute warps: 8 warps, each 64(M) x 32(N) --------
    const int lane = tid & 31, wid = tid >> 5;
    const int wm = wid >> 2, wn = wid & 3;

    // swizzled per-lane row bases (col bits 0-6 are zero -> XOR-advance by k bytes)
    unsigned rowswA[4], rowswB[2];
#pragma unroll
    for (int i = 0; i < 4; ++i) {
        int r = wm * 64 + i * 16 + (lane & 15);
        rowswA[i] = sw128((unsigned)((r >> 3) * 1024 + (r & 7) * 128));
    }
#pragma unroll
    for (int i = 0; i < 2; ++i) {
        int r = wn * 32 + i * 16 + (lane & 15);
        rowswB[i] = sw128((unsigned)((r >> 3) * 1024 + (r & 7) * 128));
    }
    const unsigned kxor = (lane >> 4) * 16;

    float acc[4][4][4];
#pragma unroll
    for (int i = 0; i < 4; ++i)
#pragma unroll
        for (int j = 0; j < 4; ++j)
#pragma unroll
            for (int k = 0; k < 4; ++k) acc[i][j][k] = 0.0f;

    int phf[2] = { 0, 0 };
    for (int c = 0; c < CH; ++c) {
        int buf = c & 1;
        MBWAIT(full[buf], phf[buf]); phf[buf] ^= 1;
        unsigned aHi = sbase + SM_SLABS + buf * BUFBYTES;
        unsigned aLo = aHi + SLAB, bHi = aHi + 2 * SLAB, bLo = aHi + 3 * SLAB;

#pragma unroll
        for (int ks = 0; ks < 4; ++ks) {
            unsigned kb = (unsigned)(ks * 32) + kxor;
            unsigned Ah[4][4], Al[4][4], Bh[2][4], Bl[2][4];
#pragma unroll
            for (int i = 0; i < 4; ++i) {
                ldsm4(Ah[i], aHi + (rowswA[i] ^ kb));
                ldsm4(Al[i], aLo + (rowswA[i] ^ kb));
            }
#pragma unroll
            for (int i = 0; i < 2; ++i) {
                ldsm4(Bh[i], bHi + (rowswB[i] ^ kb));
                ldsm4(Bl[i], bLo + (rowswB[i] ^ kb));
            }
#pragma unroll
            for (int i = 0; i < 4; ++i)
#pragma unroll
                for (int j = 0; j < 4; ++j) {
                    unsigned bh0 = Bh[j >> 1][j & 1], bh1 = Bh[j >> 1][(j & 1) + 2];
                    unsigned bl0 = Bl[j >> 1][j & 1], bl1 = Bl[j >> 1][(j & 1) + 2];
                    mma_bf16(acc[i][j], Ah[i], bh0, bh1);   // hi*hi
                    mma_bf16(acc[i][j], Ah[i], bl0, bl1);   // hi*lo
                    mma_bf16(acc[i][j], Al[i], bh0, bh1);   // lo*hi
                }
        }
        MBARRIVE(empt[buf]);
    }

    // -------- fused epilogue --------
    // acc frag: d0=(q,ct) d1=(q,ct+1) d2=(q+8,ct) d3=(q+8,ct+1); ct = 2*gsel + 4*psel
    const int gsel = lane & 1;          // 0: holds gates (g,i); 1: holds (f,o)
    const int psel = (lane >> 1) & 1;   // h-col parity within n8 tile
    const int q = lane >> 2;

    // pair exchange: each thread sends the mtiles its partner processes
    float oth[2][4][4];
#pragma unroll
    for (int i = 0; i < 2; ++i)
#pragma unroll
        for (int j = 0; j < 4; ++j)
#pragma unroll
            for (int k = 0; k < 4; ++k) {
                float sendv = gsel ? acc[i][j][k] : acc[i + 2][j][k];
                oth[i][j][k] = __shfl_xor_sync(0xFFFFFFFFu, sendv, 1);
            }

#pragma unroll
    for (int i = 0; i < 2; ++i) {
#pragma unroll
        for (int rs = 0; rs < 2; ++rs) {
            const int mp_off = (gsel ? i + 2 : i) * 16;
            const int b = m0 + wm * 64 + mp_off + q + rs * 8;
            const int dd = x[b * Tlen + t];
#pragma unroll
            for (int j = 0; j < 4; ++j) {
                float z0 = gsel ? acc[i + 2][j][rs * 2 + 0] : acc[i][j][rs * 2 + 0];
                float z1 = gsel ? acc[i + 2][j][rs * 2 + 1] : acc[i][j][rs * 2 + 1];
                float y0 = oth[i][j][rs * 2 + 0];
                float y1 = oth[i][j][rs * 2 + 1];
                float zg, zi, zf, zo;
                if (gsel == 0) { zg = z0; zi = z1; zf = y0; zo = y1; }
                else           { zg = y0; zi = y1; zf = z0; zo = z1; }

                const int col4 = wn * 32 + j * 8 + psel * 4;
                zg += sh_gx[dd * 128 + col4 + 0];
                zi += sh_gx[dd * 128 + col4 + 1];
                zf += sh_gx[dd * 128 + col4 + 2];
                zo += sh_gx[dd * 128 + col4 + 3];

                const int hcolg = nt * 32 + wn * 8 + j * 2 + psel;
                float cold = g_c[b * Hdim + hcolg];
                float cn = tanh_fast(zg) * sigf(zi) + cold * sigf(zf);
                float hn = tanh_fast(cn) * sigf(zo);
                g_c[b * Hdim + hcolg]    = cn;
                g_hfin[b * Hdim + hcolg] = hn;

                __nv_bfloat16 hh = __float2bfloat16(hn);
                __nv_bfloat16 hl = __float2bfloat16(hn - __bfloat162float(hh));
                const int chunk = hcolg >> 6, kcol = hcolg & 63;
                const int rl = b & 127;
                unsigned so = sw128((unsigned)((rl >> 3) * 1024 + (rl & 7) * 128 + kcol * 2));
                *(__nv_bfloat16*)(g_hsw[np][0][mt][chunk] + so) = hh;
                *(__nv_bfloat16*)(g_hsw[np][1][mt][chunk] + so) = hl;
            }
        }
    }
}

// ---------------- head: p = h @ Wp + bp; log_softmax ----------------
__global__ void lstm_head(const float* __restrict__ Wp,
                          const float* __restrict__ bp,
                          float* __restrict__ out) {
    int warp = threadIdx.x >> 5;
    int lane = threadIdx.x & 31;
    int row = blockIdx.x * 8 + warp;
    if (row >= Bsz) return;

    const float* __restrict__ h = &g_hfin[row * Hdim];
    float acc[NCLS];
#pragma unroll
    for (int n = 0; n < NCLS; ++n) acc[n] = 0.0f;
    for (int k = lane; k < Hdim; k += 32) {
        float hv = h[k];
#pragma unroll
        for (int n = 0; n < NCLS; ++n) acc[n] += hv * Wp[k * NCLS + n];
    }
#pragma unroll
    for (int off = 16; off > 0; off >>= 1)
#pragma unroll
        for (int n = 0; n < NCLS; ++n)
            acc[n] += __shfl_xor_sync(0xFFFFFFFFu, acc[n], off);

    if (lane == 0) {
        float p[NCLS], m = -1e30f;
#pragma unroll
        for (int n = 0; n < NCLS; ++n) { p[n] = acc[n] + bp[n]; m = fmaxf(m, p[n]); }
        float ssum = 0.0f;
#pragma unroll
        for (int n = 0; n < NCLS; ++n) ssum += expf(p[n] - m);
        float lse = m + logf(ssum);
#pragma unroll
        for (int n = 0; n < NCLS; ++n) out[row * NCLS + n] = p[n] - lse;
    }
}

extern "C" void kernel_launch(void* const* d_in, const int* in_sizes, int n_in,
                              void* d_out, int out_size) {
    const int*   x   = (const int*)  d_in[0];
    const float* emb = (const float*)d_in[1];
    const float* Wx  = (const float*)d_in[2];
    const float* Wh  = (const float*)d_in[3];
    const float* b   = (const float*)d_in[4];
    const float* Wp  = (const float*)d_in[5];
    const float* bp  = (const float*)d_in[6];
    float* out = (float*)d_out;

    cudaFuncSetAttribute(lstm_step_mma, cudaFuncAttributeMaxDynamicSharedMemorySize, SMEM_TOTAL);

    lstm_init<<<4096, 256>>>(emb, Wx, b, Wh);

    dim3 grid(NT, MT);   // 16 x 8 = 128 CTAs
    for (int t = 0; t < Tlen; ++t)
        lstm_step_mma<<<grid, 288, SMEM_TOTAL>>>(x, t);

    lstm_head<<<Bsz / 8, 256>>>(Wp, bp, out);
}

// round 5
// speedup vs baseline: 2.8292x; 2.4502x over previous
#include <cuda_runtime.h>
#include <cuda_bf16.h>
#include <math.h>

// ---------------- problem constants ----------------
#define Bsz   1024
#define Tlen  128
#define Hdim  512
#define NCLS  10

// ---------------- tiling ----------------
#define MT 8            // M tiles (1024/128)
#define NT 16           // N tiles (2048/128) in permuted gate space
#define CH 16           // K chunks (512/32)
#define SLAB8 8192      // 128 rows x 32 cols x 2B, SW64 slab

// ---------------- persistent device state (pre-swizzled) ----------------
__device__ __align__(1024) unsigned char g_Wsw[2][NT][CH][SLAB8];      // [prec][ntile][chunk] 4MB
__device__ __align__(1024) unsigned char g_hsw[2][2][MT][CH][SLAB8];   // [parity][prec][mtile][chunk] 4MB
__device__ __align__(1024) float g_cblk[MT * NT][128 * 32];            // per-CTA c tile, contiguous
__device__ float g_hfin[Bsz * Hdim];
__device__ float g_gxp[3][2048];     // permuted gate-bias table

// ---------------- PTX helpers (sm_103 plain — NO tcgen05) ----------------
__device__ __forceinline__ unsigned smem_u32(const void* p) {
    unsigned r;
    asm("{ .reg .u64 t; cvta.to.shared.u64 t, %1; cvt.u32.u64 %0, t; }" : "=r"(r) : "l"(p));
    return r;
}
__device__ __forceinline__ void bulk_g2s(unsigned dst, const void* src, unsigned bytes, unsigned mbar) {
    asm volatile("cp.async.bulk.shared::cluster.global.mbarrier::complete_tx::bytes [%0], [%1], %2, [%3];"
        :: "r"(dst), "l"(src), "r"(bytes), "r"(mbar) : "memory");
}
#define BULK_S2G(g, s, n) asm volatile("cp.async.bulk.global.shared::cta.bulk_group [%0], [%1], %2;" :: "l"(g), "r"(s), "r"(n) : "memory")
#define BULK_COMMIT() asm volatile("cp.async.bulk.commit_group;" ::: "memory")
#define BULK_WAIT0()  asm volatile("cp.async.bulk.wait_group 0;" ::: "memory")
#define MBINIT(a, c)  asm volatile("mbarrier.init.shared.b64 [%0], %1;" :: "r"(a), "r"(c) : "memory")
#define MBEXPECT(a, n) asm volatile("mbarrier.arrive.expect_tx.shared.b64 _, [%0], %1;" :: "r"(a), "r"(n) : "memory")
#define MBARRIVE(a)   asm volatile("mbarrier.arrive.shared.b64 _, [%0];" :: "r"(a) : "memory")
#define FENCE_ASYNC() asm volatile("fence.proxy.async.shared::cta;" ::: "memory")

#define MBWAIT(mbar, parity) do {                                            \
    unsigned _m = (mbar); unsigned _p = (parity); unsigned _done;            \
    asm volatile("{\n\t.reg .pred p;\n\t"                                    \
        "mbarrier.try_wait.parity.acquire.cta.shared::cta.b64 p, [%1], %2;\n\t" \
        "selp.b32 %0, 1, 0, p;\n\t}"                                         \
        : "=r"(_done) : "r"(_m), "r"(_p) : "memory");                        \
    if (!_done) {                                                            \
        asm volatile("{\n\t.reg .pred P1;\n\t"                               \
            "WL_%=:\n\t"                                                     \
            "mbarrier.try_wait.parity.acquire.cta.shared::cta.b64 P1, [%0], %1, 0x989680;\n\t" \
            "@P1 bra.uni WD_%=;\n\t"                                         \
            "bra.uni WL_%=;\n\t"                                             \
            "WD_%=:\n\t}"                                                    \
            :: "r"(_m), "r"(_p) : "memory");                                 \
    }                                                                        \
} while (0)

__device__ __forceinline__ void ldsm4(unsigned* r, unsigned addr) {
    asm volatile("ldmatrix.sync.aligned.m8n8.x4.shared.b16 {%0,%1,%2,%3}, [%4];"
        : "=r"(r[0]), "=r"(r[1]), "=r"(r[2]), "=r"(r[3]) : "r"(addr));
}
__device__ __forceinline__ void mma_bf16(float* d, const unsigned* a, unsigned b0, unsigned b1) {
    asm volatile("mma.sync.aligned.m16n8k16.row.col.f32.bf16.bf16.f32 "
        "{%0,%1,%2,%3}, {%4,%5,%6,%7}, {%8,%9}, {%0,%1,%2,%3};"
        : "+f"(d[0]), "+f"(d[1]), "+f"(d[2]), "+f"(d[3])
        : "r"(a[0]), "r"(a[1]), "r"(a[2]), "r"(a[3]), "r"(b0), "r"(b1));
}

__device__ __forceinline__ unsigned sw64(unsigned o) { return o ^ ((o >> 3) & 0x30); }
__device__ __forceinline__ float sigf(float x) { return __fdividef(1.0f, 1.0f + __expf(-x)); }
__device__ __forceinline__ float tanh_fast(float x) {
    float a = fabsf(x);
    float e = __expf(2.0f * a);
    float r = 1.0f - __fdividef(2.0f, e + 1.0f);   // inf-safe
    return copysignf(r, x);
}

// ---------------- init: zero state, build permuted+swizzled Wh hi/lo + gx table ----------------
__global__ void lstm_init(const float* __restrict__ emb,
                          const float* __restrict__ Wx,
                          const float* __restrict__ bias,
                          const float* __restrict__ Wh) {
    int i = blockIdx.x * blockDim.x + threadIdx.x;   // 0 .. 1M-1

    // Wsw: permuted c = hcol*4 + gate; SW64 slabs of 32 k-cols
    {
        int c = i >> 9;              // 0..2047
        int k = i & 511;
        int r = (c & 3) * Hdim + (c >> 2);
        float w = Wh[r * Hdim + k];
        __nv_bfloat16 hi = __float2bfloat16(w);
        __nv_bfloat16 lo = __float2bfloat16(w - __bfloat162float(hi));
        int ntile = c >> 7, rl = c & 127, chunk = k >> 5, col = k & 31;
        unsigned byte = (unsigned)((rl >> 3) * 512 + (rl & 7) * 64 + col * 2);
        unsigned so = sw64(byte);
        *(__nv_bfloat16*)(g_Wsw[0][ntile][chunk] + so) = hi;
        *(__nv_bfloat16*)(g_Wsw[1][ntile][chunk] + so) = lo;
    }
    // zero h parity-0 slabs (both precisions): 2MB = 512K words
    if (i < 524288) ((unsigned*)g_hsw[0])[i] = 0u;
    // zero c (128 tiles x 4096 floats = 512K floats)
    if (i < 524288) ((float*)g_cblk)[i] = 0.0f;
    // gx table (permuted)
    if (i < 3 * 2048) {
        int d = i >> 11, c = i & 2047;
        int r = (c & 3) * Hdim + (c >> 2);
        g_gxp[d][c] = bias[r] + Wx[r * 2 + 0] * emb[d * 2 + 0]
                              + Wx[r * 2 + 1] * emb[d * 2 + 1];
    }
}

// ---------------- one LSTM step ----------------
// smem: [0..64) full[4]+empty[4] mbars, [64] cfull, [128..1664) gx,
//       [2048..18432) c tile, [18432..34816) h stage hi/lo, [35840..) 4x32KB chunk ring
#define SM_MB     0
#define SM_CF     64
#define SM_GX     128
#define SM_C      2048
#define SM_HHI    18432
#define SM_HLO    26624
#define SM_BUF    35840
#define BUFB      32768
#define SMEM_TOTAL (SM_BUF + 4 * BUFB)   // 166912

__global__ __launch_bounds__(544, 1)
void lstm_step_mma(const int* __restrict__ x, int t) {
    extern __shared__ char smem[];
    const unsigned sbase = smem_u32(smem);
    const int tid = threadIdx.x;
    const int nt = blockIdx.x, mt = blockIdx.y;
    const int m0 = mt * 128, n0 = nt * 128;
    const int par = t & 1, np = par ^ 1;
    const int blk = mt * NT + nt;

    float* sh_gx = (float*)(smem + SM_GX);
    float* sh_c  = (float*)(smem + SM_C);
    if (tid < 384) {
        int d = tid >> 7, c = tid & 127;
        sh_gx[d * 128 + c] = g_gxp[d][n0 + c];
    }

    unsigned full[4], empt[4];
#pragma unroll
    for (int i = 0; i < 4; ++i) { full[i] = sbase + SM_MB + i * 8; empt[i] = sbase + SM_MB + 32 + i * 8; }
    const unsigned cfull = sbase + SM_CF;
    if (tid == 0) {
#pragma unroll
        for (int i = 0; i < 4; ++i) { MBINIT(full[i], 1); MBINIT(empt[i], 16); }
        MBINIT(cfull, 1);
        FENCE_ASYNC();
    }
    __syncthreads();

    const int lane = tid & 31, wid = tid >> 5;

    if (wid == 16) {
        // -------- producer warp (lane 0 only) --------
        if (lane == 0) {
            MBEXPECT(cfull, 16384);
            bulk_g2s(sbase + SM_C, g_cblk[blk], 16384, cfull);
            int phe[4] = { 0, 0, 0, 0 };
            for (int ch = 0; ch < CH; ++ch) {
                int buf = ch & 3;
                if (ch >= 4) { MBWAIT(empt[buf], phe[buf]); phe[buf] ^= 1; }
                unsigned d0 = sbase + SM_BUF + buf * BUFB;
                MBEXPECT(full[buf], BUFB);
                bulk_g2s(d0,             g_hsw[par][0][mt][ch], SLAB8, full[buf]);  // A hi
                bulk_g2s(d0 + SLAB8,     g_hsw[par][1][mt][ch], SLAB8, full[buf]);  // A lo
                bulk_g2s(d0 + 2 * SLAB8, g_Wsw[0][nt][ch],      SLAB8, full[buf]);  // B hi
                bulk_g2s(d0 + 3 * SLAB8, g_Wsw[1][nt][ch],      SLAB8, full[buf]);  // B lo
            }
        }
    } else {
        // -------- 16 compute warps: each 32(M) x 32(N) --------
        const int wm = wid >> 2, wn = wid & 3;

        unsigned aRow[2], bRow[2];
#pragma unroll
        for (int mi = 0; mi < 2; ++mi) {
            int r = wm * 32 + mi * 16 + (lane & 15);
            aRow[mi] = sw64((unsigned)((r >> 3) * 512 + (r & 7) * 64));
        }
#pragma unroll
        for (int ng = 0; ng < 2; ++ng) {
            int r = wn * 32 + ng * 16 + (lane & 15);
            bRow[ng] = sw64((unsigned)((r >> 3) * 512 + (r & 7) * 64));
        }
        const unsigned colx = (unsigned)((lane >> 4) * 16);

        float acc[2][4][4];
#pragma unroll
        for (int i = 0; i < 2; ++i)
#pragma unroll
            for (int j = 0; j < 4; ++j)
#pragma unroll
                for (int k = 0; k < 4; ++k) acc[i][j][k] = 0.0f;

        int phf[4] = { 0, 0, 0, 0 };
        for (int ch = 0; ch < CH; ++ch) {
            int buf = ch & 3;
            MBWAIT(full[buf], phf[buf]); phf[buf] ^= 1;
            unsigned aHi = sbase + SM_BUF + buf * BUFB;
            unsigned aLo = aHi + SLAB8, bHi = aHi + 2 * SLAB8, bLo = aHi + 3 * SLAB8;

#pragma unroll
            for (int kh = 0; kh < 2; ++kh) {
                unsigned kb = (unsigned)(kh * 32) + colx;
                unsigned Ah[2][4], Al[2][4], Bh[2][4], Bl[2][4];
#pragma unroll
                for (int mi = 0; mi < 2; ++mi) {
                    ldsm4(Ah[mi], aHi + (aRow[mi] ^ kb));
                    ldsm4(Al[mi], aLo + (aRow[mi] ^ kb));
                }
#pragma unroll
                for (int ng = 0; ng < 2; ++ng) {
                    ldsm4(Bh[ng], bHi + (bRow[ng] ^ kb));
                    ldsm4(Bl[ng], bLo + (bRow[ng] ^ kb));
                }
                // pass-major: hi*hi, hi*lo, lo*hi (acc reuse distance 8)
#pragma unroll
                for (int pass = 0; pass < 3; ++pass) {
#pragma unroll
                    for (int mi = 0; mi < 2; ++mi)
#pragma unroll
                        for (int nj = 0; nj < 4; ++nj) {
                            const unsigned* A = (pass == 2) ? Al[mi] : Ah[mi];
                            unsigned b0 = (pass == 1) ? Bl[nj >> 1][nj & 1] : Bh[nj >> 1][nj & 1];
                            unsigned b1 = (pass == 1) ? Bl[nj >> 1][(nj & 1) + 2] : Bh[nj >> 1][(nj & 1) + 2];
                            mma_bf16(acc[mi][nj], A, b0, b1);
                        }
                }
            }
            __syncwarp();
            if (lane == 0) MBARRIVE(empt[buf]);
        }

        // -------- fused epilogue (smem-staged) --------
        MBWAIT(cfull, 0);   // c tile present

        const int gsel = lane & 1;          // 0: own gates (g,i); 1: own (f,o)
        const int psel = (lane >> 1) & 1;   // h-col parity within n8 tile
        const int q = lane >> 2;

        float oth[4][4];
#pragma unroll
        for (int nj = 0; nj < 4; ++nj)
#pragma unroll
            for (int k = 0; k < 4; ++k) {
                float sendv = gsel ? acc[0][nj][k] : acc[1][nj][k];   // partner's mi block
                oth[nj][k] = __shfl_xor_sync(0xFFFFFFFFu, sendv, 1);
            }

#pragma unroll
        for (int rh = 0; rh < 2; ++rh) {
            const int row = wm * 32 + gsel * 16 + rh * 8 + q;
            const int b = m0 + row;
            const int dd = x[b * Tlen + t];
#pragma unroll
            for (int nj = 0; nj < 4; ++nj) {
                float own0 = gsel ? acc[1][nj][rh * 2 + 0] : acc[0][nj][rh * 2 + 0];
                float own1 = gsel ? acc[1][nj][rh * 2 + 1] : acc[0][nj][rh * 2 + 1];
                float o0 = oth[nj][rh * 2 + 0];
                float o1 = oth[nj][rh * 2 + 1];
                float zg = gsel ? o0 : own0;
                float zi = gsel ? o1 : own1;
                float zf = gsel ? own0 : o0;
                float zo = gsel ? own1 : o1;

                const int hcol = wn * 8 + nj * 2 + psel;
                const int gxb = dd * 128 + hcol * 4;
                zg += sh_gx[gxb + 0];
                zi += sh_gx[gxb + 1];
                zf += sh_gx[gxb + 2];
                zo += sh_gx[gxb + 3];

                const int cidx = row * 32 + hcol;
                float cold = sh_c[cidx];
                float cn = tanh_fast(zg) * sigf(zi) + cold * sigf(zf);
                float hn = tanh_fast(cn) * sigf(zo);
                sh_c[cidx] = cn;

                __nv_bfloat16 hh = __float2bfloat16(hn);
                __nv_bfloat16 hl = __float2bfloat16(hn - __bfloat162float(hh));
                unsigned so = sw64((unsigned)((row >> 3) * 512 + (row & 7) * 64 + hcol * 2));
                *(__nv_bfloat16*)(smem + SM_HHI + so) = hh;
                *(__nv_bfloat16*)(smem + SM_HLO + so) = hl;

                if (t == Tlen - 1)
                    g_hfin[b * Hdim + nt * 32 + hcol] = hn;
            }
        }
    }

    __syncthreads();
    // bulk store: h hi/lo slabs (next step's A chunk nt of mtile mt) + c tile
    if (tid == 0) {
        FENCE_ASYNC();
        BULK_S2G((void*)g_hsw[np][0][mt][nt], sbase + SM_HHI, SLAB8);
        BULK_S2G((void*)g_hsw[np][1][mt][nt], sbase + SM_HLO, SLAB8);
        BULK_S2G((void*)g_cblk[blk], sbase + SM_C, 16384);
        BULK_COMMIT();
        BULK_WAIT0();
    }
}

// ---------------- head: p = h @ Wp + bp; log_softmax ----------------
__global__ void lstm_head(const float* __restrict__ Wp,
                          const float* __restrict__ bp,
                          float* __restrict__ out) {
    int warp = threadIdx.x >> 5;
    int lane = threadIdx.x & 31;
    int row = blockIdx.x * 8 + warp;
    if (row >= Bsz) return;

    const float* __restrict__ h = &g_hfin[row * Hdim];
    float acc[NCLS];
#pragma unroll
    for (int n = 0; n < NCLS; ++n) acc[n] = 0.0f;
    for (int k = lane; k < Hdim; k += 32) {
        float hv = h[k];
#pragma unroll
        for (int n = 0; n < NCLS; ++n) acc[n] += hv * Wp[k * NCLS + n];
    }
#pragma unroll
    for (int off = 16; off > 0; off >>= 1)
#pragma unroll
        for (int n = 0; n < NCLS; ++n)
            acc[n] += __shfl_xor_sync(0xFFFFFFFFu, acc[n], off);

    if (lane == 0) {
        float p[NCLS], m = -1e30f;
#pragma unroll
        for (int n = 0; n < NCLS; ++n) { p[n] = acc[n] + bp[n]; m = fmaxf(m, p[n]); }
        float ssum = 0.0f;
#pragma unroll
        for (int n = 0; n < NCLS; ++n) ssum += expf(p[n] - m);
        float lse = m + logf(ssum);
#pragma unroll
        for (int n = 0; n < NCLS; ++n) out[row * NCLS + n] = p[n] - lse;
    }
}

extern "C" void kernel_launch(void* const* d_in, const int* in_sizes, int n_in,
                              void* d_out, int out_size) {
    const int*   x   = (const int*)  d_in[0];
    const float* emb = (const float*)d_in[1];
    const float* Wx  = (const float*)d_in[2];
    const float* Wh  = (const float*)d_in[3];
    const float* b   = (const float*)d_in[4];
    const float* Wp  = (const float*)d_in[5];
    const float* bp  = (const float*)d_in[6];
    float* out = (float*)d_out;

    cudaFuncSetAttribute(lstm_step_mma, cudaFuncAttributeMaxDynamicSharedMemorySize, SMEM_TOTAL);

    lstm_init<<<4096, 256>>>(emb, Wx, b, Wh);

    dim3 grid(NT, MT);   // 16 x 8 = 128 CTAs
    for (int t = 0; t < Tlen; ++t)
        lstm_step_mma<<<grid, 544, SMEM_TOTAL>>>(x, t);

    lstm_head<<<Bsz / 8, 256>>>(Wp, bp, out);
}

// round 6
// speedup vs baseline: 2.9388x; 1.0388x over previous
#include <cuda_runtime.h>
#include <cuda_bf16.h>
#include <math.h>

// ---------------- problem constants ----------------
#define Bsz   1024
#define Tlen  128
#define Hdim  512
#define NCLS  10

// ---------------- tiling ----------------
#define MT 8            // M tiles (1024/128)
#define NT 16           // N tiles (2048/128) in permuted gate space
#define CH 16           // K chunks (512/32)
#define SLAB8 8192      // 128 rows x 32 cols x 2B, SW64 slab

// ---------------- persistent device state (pre-swizzled) ----------------
__device__ __align__(1024) unsigned char g_Wsw[2][NT][CH][SLAB8];      // [prec][ntile][chunk] 4MB
__device__ __align__(1024) unsigned char g_hsw[2][2][MT][CH][SLAB8];   // [parity][prec][mtile][chunk] 4MB
__device__ float g_hfin[Bsz * Hdim];
__device__ float g_gxp[3][2048];     // permuted gate-bias table
__device__ unsigned g_barcnt;
__device__ volatile unsigned g_barsense;

// ---------------- PTX helpers (sm_103 plain — NO tcgen05) ----------------
__device__ __forceinline__ unsigned smem_u32(const void* p) {
    unsigned r;
    asm("{ .reg .u64 t; cvta.to.shared.u64 t, %1; cvt.u32.u64 %0, t; }" : "=r"(r) : "l"(p));
    return r;
}
__device__ __forceinline__ void bulk_g2s(unsigned dst, const void* src, unsigned bytes, unsigned mbar) {
    asm volatile("cp.async.bulk.shared::cluster.global.mbarrier::complete_tx::bytes [%0], [%1], %2, [%3];"
        :: "r"(dst), "l"(src), "r"(bytes), "r"(mbar) : "memory");
}
#define BULK_S2G(g, s, n) asm volatile("cp.async.bulk.global.shared::cta.bulk_group [%0], [%1], %2;" :: "l"(g), "r"(s), "r"(n) : "memory")
#define BULK_COMMIT() asm volatile("cp.async.bulk.commit_group;" ::: "memory")
#define BULK_WAIT0()  asm volatile("cp.async.bulk.wait_group 0;" ::: "memory")
#define MBINIT(a, c)  asm volatile("mbarrier.init.shared.b64 [%0], %1;" :: "r"(a), "r"(c) : "memory")
#define MBEXPECT(a, n) asm volatile("mbarrier.arrive.expect_tx.shared.b64 _, [%0], %1;" :: "r"(a), "r"(n) : "memory")
#define MBARRIVE(a)   asm volatile("mbarrier.arrive.shared.b64 _, [%0];" :: "r"(a) : "memory")
#define FENCE_ASYNC() asm volatile("fence.proxy.async.shared::cta;" ::: "memory")

#define MBWAIT(mbar, parity) do {                                            \
    unsigned _m = (mbar); unsigned _p = (parity); unsigned _done;            \
    asm volatile("{\n\t.reg .pred p;\n\t"                                    \
        "mbarrier.try_wait.parity.acquire.cta.shared::cta.b64 p, [%1], %2;\n\t" \
        "selp.b32 %0, 1, 0, p;\n\t}"                                         \
        : "=r"(_done) : "r"(_m), "r"(_p) : "memory");                        \
    if (!_done) {                                                            \
        asm volatile("{\n\t.reg .pred P1;\n\t"                               \
            "WL_%=:\n\t"                                                     \
            "mbarrier.try_wait.parity.acquire.cta.shared::cta.b64 P1, [%0], %1, 0x989680;\n\t" \
            "@P1 bra.uni WD_%=;\n\t"                                         \
            "bra.uni WL_%=;\n\t"                                             \
            "WD_%=:\n\t}"                                                    \
            :: "r"(_m), "r"(_p) : "memory");                                 \
    }                                                                        \
} while (0)

__device__ __forceinline__ void ldsm4(unsigned* r, unsigned addr) {
    asm volatile("ldmatrix.sync.aligned.m8n8.x4.shared.b16 {%0,%1,%2,%3}, [%4];"
        : "=r"(r[0]), "=r"(r[1]), "=r"(r[2]), "=r"(r[3]) : "r"(addr));
}
__device__ __forceinline__ void mma_bf16(float* d, const unsigned* a, unsigned b0, unsigned b1) {
    asm volatile("mma.sync.aligned.m16n8k16.row.col.f32.bf16.bf16.f32 "
        "{%0,%1,%2,%3}, {%4,%5,%6,%7}, {%8,%9}, {%0,%1,%2,%3};"
        : "+f"(d[0]), "+f"(d[1]), "+f"(d[2]), "+f"(d[3])
        : "r"(a[0]), "r"(a[1]), "r"(a[2]), "r"(a[3]), "r"(b0), "r"(b1));
}

__device__ __forceinline__ unsigned sw64(unsigned o) { return o ^ ((o >> 3) & 0x30); }
__device__ __forceinline__ float sigf(float x) { return __fdividef(1.0f, 1.0f + __expf(-x)); }
__device__ __forceinline__ float tanh_fast(float x) {
    float a = fabsf(x);
    float e = __expf(2.0f * a);
    float r = 1.0f - __fdividef(2.0f, e + 1.0f);   // inf-safe
    return copysignf(r, x);
}

// ---------------- init: zero state, build permuted+swizzled Wh hi/lo + gx table ----------------
__global__ void lstm_init(const float* __restrict__ emb,
                          const float* __restrict__ Wx,
                          const float* __restrict__ bias,
                          const float* __restrict__ Wh) {
    int i = blockIdx.x * blockDim.x + threadIdx.x;   // 0 .. 1M-1

    // Wsw: permuted c = hcol*4 + gate; SW64 slabs of 32 k-cols
    {
        int c = i >> 9;              // 0..2047
        int k = i & 511;
        int r = (c & 3) * Hdim + (c >> 2);
        float w = Wh[r * Hdim + k];
        __nv_bfloat16 hi = __float2bfloat16(w);
        __nv_bfloat16 lo = __float2bfloat16(w - __bfloat162float(hi));
        int ntile = c >> 7, rl = c & 127, chunk = k >> 5, col = k & 31;
        unsigned byte = (unsigned)((rl >> 3) * 512 + (rl & 7) * 64 + col * 2);
        unsigned so = sw64(byte);
        *(__nv_bfloat16*)(g_Wsw[0][ntile][chunk] + so) = hi;
        *(__nv_bfloat16*)(g_Wsw[1][ntile][chunk] + so) = lo;
    }
    // zero h parity-0 slabs (both precisions): 2MB = 512K words
    if (i < 524288) ((unsigned*)g_hsw[0])[i] = 0u;
    // gx table (permuted)
    if (i < 3 * 2048) {
        int d = i >> 11, c = i & 2047;
        int r = (c & 3) * Hdim + (c >> 2);
        g_gxp[d][c] = bias[r] + Wx[r * 2 + 0] * emb[d * 2 + 0]
                              + Wx[r * 2 + 1] * emb[d * 2 + 1];
    }
    if (i == 0) { g_barcnt = 0; g_barsense = 0u; }
}

// ---------------- persistent LSTM: all 128 steps in one kernel ----------------
// smem: [0..64) full[4]+empty[4] mbars, [128..1664) gx,
//       [2048..18432) c tile, [18432..34816) h stage hi/lo, [35840..) 4x32KB chunk ring
#define SM_MB     0
#define SM_GX     128
#define SM_C      2048
#define SM_HHI    18432
#define SM_HLO    26624
#define SM_BUF    35840
#define BUFB      32768
#define SMEM_TOTAL (SM_BUF + 4 * BUFB)   // 166912

__global__ __launch_bounds__(544, 1)
void lstm_persist(const int* __restrict__ x) {
    extern __shared__ char smem[];
    const unsigned sbase = smem_u32(smem);
    const int tid = threadIdx.x;
    const int nt = blockIdx.x, mt = blockIdx.y;
    const int m0 = mt * 128, n0 = nt * 128;

    float* sh_gx = (float*)(smem + SM_GX);
    float* sh_c  = (float*)(smem + SM_C);
    if (tid < 384) {
        int d = tid >> 7, c = tid & 127;
        sh_gx[d * 128 + c] = g_gxp[d][n0 + c];
    }
    for (int i = tid; i < 128 * 32; i += 544) sh_c[i] = 0.0f;

    unsigned full[4], empt[4];
#pragma unroll
    for (int i = 0; i < 4; ++i) { full[i] = sbase + SM_MB + i * 8; empt[i] = sbase + SM_MB + 32 + i * 8; }
    if (tid == 0) {
#pragma unroll
        for (int i = 0; i < 4; ++i) { MBINIT(full[i], 1); MBINIT(empt[i], 16); }
        FENCE_ASYNC();
    }
    __syncthreads();

    const int lane = tid & 31, wid = tid >> 5;

    // ---- compute-warp constants (valid for wid < 16) ----
    const int wm = wid >> 2, wn = wid & 3;
    unsigned aRow[2], bRow[2];
#pragma unroll
    for (int mi = 0; mi < 2; ++mi) {
        int r = wm * 32 + mi * 16 + (lane & 15);
        aRow[mi] = sw64((unsigned)((r >> 3) * 512 + (r & 7) * 64));
    }
#pragma unroll
    for (int ng = 0; ng < 2; ++ng) {
        int r = wn * 32 + ng * 16 + (lane & 15);
        bRow[ng] = sw64((unsigned)((r >> 3) * 512 + (r & 7) * 64));
    }
    const unsigned colx = (unsigned)((lane >> 4) * 16);
    const int gsel = lane & 1;
    const int psel = (lane >> 1) & 1;
    const int q = lane >> 2;

    unsigned lsense = 0;

    for (int t = 0; t < Tlen; ++t) {
        const int par = t & 1, np = par ^ 1;

        if (wid == 16) {
            // -------- producer warp (lane 0 only) --------
            if (lane == 0) {
                for (int ch = 0; ch < CH; ++ch) {
                    int buf = ch & 3;
                    unsigned pe = ((ch >> 2) & 1) ^ 1;      // empty-wait parity (first passes)
                    MBWAIT(empt[buf], pe);
                    unsigned d0 = sbase + SM_BUF + buf * BUFB;
                    MBEXPECT(full[buf], BUFB);
                    bulk_g2s(d0,             g_hsw[par][0][mt][ch], SLAB8, full[buf]);  // A hi
                    bulk_g2s(d0 + SLAB8,     g_hsw[par][1][mt][ch], SLAB8, full[buf]);  // A lo
                    bulk_g2s(d0 + 2 * SLAB8, g_Wsw[0][nt][ch],      SLAB8, full[buf]);  // B hi
                    bulk_g2s(d0 + 3 * SLAB8, g_Wsw[1][nt][ch],      SLAB8, full[buf]);  // B lo
                }
            }
        } else {
            // -------- 16 compute warps: each 32(M) x 32(N) --------
            float acc[2][4][4];
#pragma unroll
            for (int i = 0; i < 2; ++i)
#pragma unroll
                for (int j = 0; j < 4; ++j)
#pragma unroll
                    for (int k = 0; k < 4; ++k) acc[i][j][k] = 0.0f;

#pragma unroll 4
            for (int ch = 0; ch < CH; ++ch) {
                int buf = ch & 3;
                unsigned pf = (ch >> 2) & 1;                // full-wait parity
                MBWAIT(full[buf], pf);
                unsigned aHi = sbase + SM_BUF + buf * BUFB;
                unsigned aLo = aHi + SLAB8, bHi = aHi + 2 * SLAB8, bLo = aHi + 3 * SLAB8;

#pragma unroll
                for (int kh = 0; kh < 2; ++kh) {
                    unsigned kb = (unsigned)(kh * 32) + colx;
                    unsigned Ah[2][4], Al[2][4], Bh[2][4], Bl[2][4];
#pragma unroll
                    for (int mi = 0; mi < 2; ++mi) {
                        ldsm4(Ah[mi], aHi + (aRow[mi] ^ kb));
                        ldsm4(Al[mi], aLo + (aRow[mi] ^ kb));
                    }
#pragma unroll
                    for (int ng = 0; ng < 2; ++ng) {
                        ldsm4(Bh[ng], bHi + (bRow[ng] ^ kb));
                        ldsm4(Bl[ng], bLo + (bRow[ng] ^ kb));
                    }
                    // pass-major: hi*hi, hi*lo, lo*hi (acc reuse distance 8)
#pragma unroll
                    for (int pass = 0; pass < 3; ++pass) {
#pragma unroll
                        for (int mi = 0; mi < 2; ++mi)
#pragma unroll
                            for (int nj = 0; nj < 4; ++nj) {
                                const unsigned* A = (pass == 2) ? Al[mi] : Ah[mi];
                                unsigned b0 = (pass == 1) ? Bl[nj >> 1][nj & 1] : Bh[nj >> 1][nj & 1];
                                unsigned b1 = (pass == 1) ? Bl[nj >> 1][(nj & 1) + 2] : Bh[nj >> 1][(nj & 1) + 2];
                                mma_bf16(acc[mi][nj], A, b0, b1);
                            }
                    }
                }
                __syncwarp();
                if (lane == 0) MBARRIVE(empt[buf]);
            }

            // -------- fused epilogue (smem c, smem h stage) --------
            float oth[4][4];
#pragma unroll
            for (int nj = 0; nj < 4; ++nj)
#pragma unroll
                for (int k = 0; k < 4; ++k) {
                    float sendv = gsel ? acc[0][nj][k] : acc[1][nj][k];
                    oth[nj][k] = __shfl_xor_sync(0xFFFFFFFFu, sendv, 1);
                }

#pragma unroll
            for (int rh = 0; rh < 2; ++rh) {
                const int row = wm * 32 + gsel * 16 + rh * 8 + q;
                const int b = m0 + row;
                const int dd = x[b * Tlen + t];
#pragma unroll
                for (int nj = 0; nj < 4; ++nj) {
                    float own0 = gsel ? acc[1][nj][rh * 2 + 0] : acc[0][nj][rh * 2 + 0];
                    float own1 = gsel ? acc[1][nj][rh * 2 + 1] : acc[0][nj][rh * 2 + 1];
                    float o0 = oth[nj][rh * 2 + 0];
                    float o1 = oth[nj][rh * 2 + 1];
                    float zg = gsel ? o0 : own0;
                    float zi = gsel ? o1 : own1;
                    float zf = gsel ? own0 : o0;
                    float zo = gsel ? own1 : o1;

                    const int hcol = wn * 8 + nj * 2 + psel;
                    const int gxb = dd * 128 + hcol * 4;
                    zg += sh_gx[gxb + 0];
                    zi += sh_gx[gxb + 1];
                    zf += sh_gx[gxb + 2];
                    zo += sh_gx[gxb + 3];

                    const int cidx = row * 32 + hcol;
                    float cold = sh_c[cidx];
                    float cn = tanh_fast(zg) * sigf(zi) + cold * sigf(zf);
                    float hn = tanh_fast(cn) * sigf(zo);
                    sh_c[cidx] = cn;

                    __nv_bfloat16 hh = __float2bfloat16(hn);
                    __nv_bfloat16 hl = __float2bfloat16(hn - __bfloat162float(hh));
                    unsigned so = sw64((unsigned)((row >> 3) * 512 + (row & 7) * 64 + hcol * 2));
                    *(__nv_bfloat16*)(smem + SM_HHI + so) = hh;
                    *(__nv_bfloat16*)(smem + SM_HLO + so) = hl;

                    if (t == Tlen - 1)
                        g_hfin[b * Hdim + nt * 32 + hcol] = hn;
                }
            }
        }

        __syncthreads();
        if (tid == 0) {
            // publish h slabs for next step
            FENCE_ASYNC();
            BULK_S2G((void*)g_hsw[np][0][mt][nt], sbase + SM_HHI, SLAB8);
            BULK_S2G((void*)g_hsw[np][1][mt][nt], sbase + SM_HLO, SLAB8);
            BULK_COMMIT();
            BULK_WAIT0();
            __threadfence();
            // grid barrier (sense reversal; 128 co-resident CTAs)
            unsigned s = lsense ^ 1u;
            if (atomicAdd(&g_barcnt, 1u) == (unsigned)(MT * NT - 1)) {
                g_barcnt = 0u;
                __threadfence();
                g_barsense = s;
            } else {
                while (g_barsense != s) { }
            }
            lsense = s;
        }
        __syncthreads();
    }
}

// ---------------- head: p = h @ Wp + bp; log_softmax ----------------
__global__ void lstm_head(const float* __restrict__ Wp,
                          const float* __restrict__ bp,
                          float* __restrict__ out) {
    int warp = threadIdx.x >> 5;
    int lane = threadIdx.x & 31;
    int row = blockIdx.x * 8 + warp;
    if (row >= Bsz) return;

    const float* __restrict__ h = &g_hfin[row * Hdim];
    float acc[NCLS];
#pragma unroll
    for (int n = 0; n < NCLS; ++n) acc[n] = 0.0f;
    for (int k = lane; k < Hdim; k += 32) {
        float hv = h[k];
#pragma unroll
        for (int n = 0; n < NCLS; ++n) acc[n] += hv * Wp[k * NCLS + n];
    }
#pragma unroll
    for (int off = 16; off > 0; off >>= 1)
#pragma unroll
        for (int n = 0; n < NCLS; ++n)
            acc[n] += __shfl_xor_sync(0xFFFFFFFFu, acc[n], off);

    if (lane == 0) {
        float p[NCLS], m = -1e30f;
#pragma unroll
        for (int n = 0; n < NCLS; ++n) { p[n] = acc[n] + bp[n]; m = fmaxf(m, p[n]); }
        float ssum = 0.0f;
#pragma unroll
        for (int n = 0; n < NCLS; ++n) ssum += expf(p[n] - m);
        float lse = m + logf(ssum);
#pragma unroll
        for (int n = 0; n < NCLS; ++n) out[row * NCLS + n] = p[n] - lse;
    }
}

extern "C" void kernel_launch(void* const* d_in, const int* in_sizes, int n_in,
                              void* d_out, int out_size) {
    const int*   x   = (const int*)  d_in[0];
    const float* emb = (const float*)d_in[1];
    const float* Wx  = (const float*)d_in[2];
    const float* Wh  = (const float*)d_in[3];
    const float* b   = (const float*)d_in[4];
    const float* Wp  = (const float*)d_in[5];
    const float* bp  = (const float*)d_in[6];
    float* out = (float*)d_out;

    cudaFuncSetAttribute(lstm_persist, cudaFuncAttributeMaxDynamicSharedMemorySize, SMEM_TOTAL);

    lstm_init<<<4096, 256>>>(emb, Wx, b, Wh);

    dim3 grid(NT, MT);   // 16 x 8 = 128 CTAs, 1 per SM -> co-resident
    lstm_persist<<<grid, 544, SMEM_TOTAL>>>(x);

    lstm_head<<<Bsz / 8, 256>>>(Wp, bp, out);
}

// round 8
// speedup vs baseline: 3.7904x; 1.2898x over previous
#include <cuda_runtime.h>
#include <cuda_fp16.h>
#include <math.h>

// ---------------- problem constants ----------------
#define Bsz   1024
#define Tlen  128
#define Hdim  512
#define NCLS  10

// ---------------- tiling ----------------
#define MT 8            // M tiles (1024/128)
#define NT 16           // N tiles (2048/128) in permuted gate space
#define CH 16           // K chunks (512/32)
#define SLAB8 8192      // 128 rows x 32 cols x 2B, SW64 slab

// ---------------- persistent device state (pre-swizzled) ----------------
__device__ __align__(1024) unsigned char g_Wsw[NT][CH][SLAB8];         // fp16 W, 2MB
__device__ __align__(1024) unsigned char g_hsw[2][2][MT][CH][SLAB8];   // [parity][hi/lo][mtile][chunk] 4MB (fp16)
__device__ float g_hfin[Bsz * Hdim];
__device__ float g_gxp[3][2048];     // permuted gate-bias table
__device__ unsigned g_rowbar[MT * 32];
__device__ volatile unsigned g_rowsense[MT * 32];

// ---------------- PTX helpers (sm_103 plain — NO tcgen05) ----------------
__device__ __forceinline__ unsigned smem_u32(const void* p) {
    unsigned r;
    asm("{ .reg .u64 t; cvta.to.shared.u64 t, %1; cvt.u32.u64 %0, t; }" : "=r"(r) : "l"(p));
    return r;
}
__device__ __forceinline__ void bulk_g2s(unsigned dst, const void* src, unsigned bytes, unsigned mbar) {
    asm volatile("cp.async.bulk.shared::cluster.global.mbarrier::complete_tx::bytes [%0], [%1], %2, [%3];"
        :: "r"(dst), "l"(src), "r"(bytes), "r"(mbar) : "memory");
}
#define BULK_S2G(g, s, n) asm volatile("cp.async.bulk.global.shared::cta.bulk_group [%0], [%1], %2;" :: "l"(g), "r"(s), "r"(n) : "memory")
#define BULK_COMMIT() asm volatile("cp.async.bulk.commit_group;" ::: "memory")
#define BULK_WAIT0()  asm volatile("cp.async.bulk.wait_group 0;" ::: "memory")
#define MBINIT(a, c)  asm volatile("mbarrier.init.shared.b64 [%0], %1;" :: "r"(a), "r"(c) : "memory")
#define MBEXPECT(a, n) asm volatile("mbarrier.arrive.expect_tx.shared.b64 _, [%0], %1;" :: "r"(a), "r"(n) : "memory")
#define MBARRIVE(a)   asm volatile("mbarrier.arrive.shared.b64 _, [%0];" :: "r"(a) : "memory")
#define FENCE_ASYNC() asm volatile("fence.proxy.async.shared::cta;" ::: "memory")

#define MBWAIT(mbar, parity) do {                                            \
    unsigned _m = (mbar); unsigned _p = (parity); unsigned _done;            \
    asm volatile("{\n\t.reg .pred p;\n\t"                                    \
        "mbarrier.try_wait.parity.acquire.cta.shared::cta.b64 p, [%1], %2;\n\t" \
        "selp.b32 %0, 1, 0, p;\n\t}"                                         \
        : "=r"(_done) : "r"(_m), "r"(_p) : "memory");                        \
    if (!_done) {                                                            \
        asm volatile("{\n\t.reg .pred P1;\n\t"                               \
            "WL_%=:\n\t"                                                     \
            "mbarrier.try_wait.parity.acquire.cta.shared::cta.b64 P1, [%0], %1, 0x989680;\n\t" \
            "@P1 bra.uni WD_%=;\n\t"                                         \
            "bra.uni WL_%=;\n\t"                                             \
            "WD_%=:\n\t}"                                                    \
            :: "r"(_m), "r"(_p) : "memory");                                 \
    }                                                                        \
} while (0)

__device__ __forceinline__ void ldsm4(unsigned* r, unsigned addr) {
    asm volatile("ldmatrix.sync.aligned.m8n8.x4.shared.b16 {%0,%1,%2,%3}, [%4];"
        : "=r"(r[0]), "=r"(r[1]), "=r"(r[2]), "=r"(r[3]) : "r"(addr));
}
__device__ __forceinline__ void mma_f16(float* d, const unsigned* a, unsigned b0, unsigned b1) {
    asm volatile("mma.sync.aligned.m16n8k16.row.col.f32.f16.f16.f32 "
        "{%0,%1,%2,%3}, {%4,%5,%6,%7}, {%8,%9}, {%0,%1,%2,%3};"
        : "+f"(d[0]), "+f"(d[1]), "+f"(d[2]), "+f"(d[3])
        : "r"(a[0]), "r"(a[1]), "r"(a[2]), "r"(a[3]), "r"(b0), "r"(b1));
}

__device__ __forceinline__ unsigned sw64(unsigned o) { return o ^ ((o >> 3) & 0x30); }
__device__ __forceinline__ float sigf(float x) { return __fdividef(1.0f, 1.0f + __expf(-x)); }
__device__ __forceinline__ float tanh_fast(float x) {
    float a = fabsf(x);
    float e = __expf(2.0f * a);
    float r = 1.0f - __fdividef(2.0f, e + 1.0f);   // inf-safe
    return copysignf(r, x);
}

// ---------------- init ----------------
__global__ void lstm_init(const float* __restrict__ emb,
                          const float* __restrict__ Wx,
                          const float* __restrict__ bias,
                          const float* __restrict__ Wh) {
    int i = blockIdx.x * blockDim.x + threadIdx.x;   // 0 .. 1M-1

    // Wsw: permuted c = hcol*4 + gate; SW64 slabs of 32 k-cols; single fp16
    {
        int c = i >> 9;              // 0..2047
        int k = i & 511;
        int r = (c & 3) * Hdim + (c >> 2);
        float w = Wh[r * Hdim + k];
        int ntile = c >> 7, rl = c & 127, chunk = k >> 5, col = k & 31;
        unsigned byte = (unsigned)((rl >> 3) * 512 + (rl & 7) * 64 + col * 2);
        unsigned so = sw64(byte);
        *(__half*)(g_Wsw[ntile][chunk] + so) = __float2half(w);
    }
    // zero h parity-0 slabs (hi+lo): 2MB = 512K words
    if (i < 524288) ((unsigned*)g_hsw[0])[i] = 0u;
    // gx table (permuted)
    if (i < 3 * 2048) {
        int d = i >> 11, c = i & 2047;
        int r = (c & 3) * Hdim + (c >> 2);
        g_gxp[d][c] = bias[r] + Wx[r * 2 + 0] * emb[d * 2 + 0]
                              + Wx[r * 2 + 1] * emb[d * 2 + 1];
    }
    if (i < MT * 32) { g_rowbar[i] = 0u; g_rowsense[i] = 0u; }
}

// ---------------- persistent LSTM ----------------
// smem: [0..64) full[4]+empty[4], [64] wbar, [128..1664) gx,
//       [2048..18432) c, [18432..34816) h stage hi/lo, [34816..165888) W resident,
//       [165888..231424) 4x16KB A ring
#define SM_MB     0
#define SM_WBAR   64
#define SM_GX     128
#define SM_C      2048
#define SM_HHI    18432
#define SM_HLO    26624
#define SM_W      34816
#define SM_ABUF   165888
#define ABUFB     16384
#define SMEM_TOTAL (SM_ABUF + 4 * ABUFB)   // 231424

__global__ __launch_bounds__(544, 1)
void lstm_persist(const int* __restrict__ x) {
    extern __shared__ char smem[];
    const unsigned sbase = smem_u32(smem);
    const int tid = threadIdx.x;
    const int nt = blockIdx.x, mt = blockIdx.y;
    const int m0 = mt * 128, n0 = nt * 128;

    float* sh_gx = (float*)(smem + SM_GX);
    float* sh_c  = (float*)(smem + SM_C);
    if (tid < 384) {
        int d = tid >> 7, c = tid & 127;
        sh_gx[d * 128 + c] = g_gxp[d][n0 + c];
    }
    for (int i = tid; i < 128 * 32; i += 544) sh_c[i] = 0.0f;

    unsigned full[4], empt[4];
#pragma unroll
    for (int i = 0; i < 4; ++i) { full[i] = sbase + SM_MB + i * 8; empt[i] = sbase + SM_MB + 32 + i * 8; }
    const unsigned wbar = sbase + SM_WBAR;
    if (tid == 0) {
#pragma unroll
        for (int i = 0; i < 4; ++i) { MBINIT(full[i], 1); MBINIT(empt[i], 16); }
        MBINIT(wbar, 1);
        FENCE_ASYNC();
    }
    __syncthreads();

    // one-time W residency load (128KB contiguous)
    if (tid == 0) {
        MBEXPECT(wbar, 16 * SLAB8);
        bulk_g2s(sbase + SM_W, g_Wsw[nt], 16 * SLAB8, wbar);
    }

    const int lane = tid & 31, wid = tid >> 5;

    // ---- compute-warp constants (valid for wid < 16) ----
    const int wm = wid >> 2, wn = wid & 3;
    unsigned aRow[2], bRowSw[2];
#pragma unroll
    for (int mi = 0; mi < 2; ++mi) {
        int r = wm * 32 + mi * 16 + (lane & 15);
        aRow[mi] = sw64((unsigned)((r >> 3) * 512 + (r & 7) * 64));
    }
#pragma unroll
    for (int ng = 0; ng < 2; ++ng) {
        int r = wn * 32 + ng * 16 + (lane & 15);
        // swizzled row offset kept SEPARATE: XOR with kb must happen before
        // adding the base (sw64 sets bits [4:5]; ADD would carry into bit 6)
        bRowSw[ng] = sw64((unsigned)((r >> 3) * 512 + (r & 7) * 64));
    }
    const unsigned wbase = sbase + SM_W;
    const unsigned colx = (unsigned)((lane >> 4) * 16);
    const int gsel = lane & 1;
    const int psel = (lane >> 1) & 1;
    const int q = lane >> 2;

    if (wid < 16) MBWAIT(wbar, 0);   // W resident before first B ldsm

    unsigned lsense = 0;

    for (int t = 0; t < Tlen; ++t) {
        const int par = t & 1, np = par ^ 1;

        if (wid == 16) {
            // -------- producer warp (lane 0 only): A hi/lo chunks --------
            if (lane == 0) {
                for (int ch = 0; ch < CH; ++ch) {
                    int buf = ch & 3;
                    unsigned pe = ((ch >> 2) & 1) ^ 1;      // empty-wait parity
                    MBWAIT(empt[buf], pe);
                    unsigned d0 = sbase + SM_ABUF + buf * ABUFB;
                    MBEXPECT(full[buf], ABUFB);
                    bulk_g2s(d0,         g_hsw[par][0][mt][ch], SLAB8, full[buf]);  // A hi
                    bulk_g2s(d0 + SLAB8, g_hsw[par][1][mt][ch], SLAB8, full[buf]);  // A lo
                }
            }
        } else {
            // -------- x prefetch for this step --------
            int ddv[2];
#pragma unroll
            for (int rh = 0; rh < 2; ++rh) {
                int row = wm * 32 + gsel * 16 + rh * 8 + q;
                ddv[rh] = x[(m0 + row) * Tlen + t];
            }

            // -------- 16 compute warps: each 32(M) x 32(N) --------
            float acc[2][4][4];
#pragma unroll
            for (int i = 0; i < 2; ++i)
#pragma unroll
                for (int j = 0; j < 4; ++j)
#pragma unroll
                    for (int k = 0; k < 4; ++k) acc[i][j][k] = 0.0f;

#pragma unroll 4
            for (int ch = 0; ch < CH; ++ch) {
                int buf = ch & 3;
                unsigned pf = (ch >> 2) & 1;                // full-wait parity
                MBWAIT(full[buf], pf);
                unsigned aHi = sbase + SM_ABUF + buf * ABUFB;
                unsigned aLo = aHi + SLAB8;
                unsigned bB  = wbase + (unsigned)(ch * SLAB8);

#pragma unroll
                for (int kh = 0; kh < 2; ++kh) {
                    unsigned kb = (unsigned)(kh * 32) + colx;
                    unsigned Ah[2][4], Al[2][4], Bf[2][4];
#pragma unroll
                    for (int mi = 0; mi < 2; ++mi) {
                        ldsm4(Ah[mi], aHi + (aRow[mi] ^ kb));
                        ldsm4(Al[mi], aLo + (aRow[mi] ^ kb));
                    }
#pragma unroll
                    for (int ng = 0; ng < 2; ++ng)
                        ldsm4(Bf[ng], bB + (bRowSw[ng] ^ kb));   // FIX: XOR before base add
#pragma unroll
                    for (int pass = 0; pass < 2; ++pass) {
#pragma unroll
                        for (int mi = 0; mi < 2; ++mi)
#pragma unroll
                            for (int nj = 0; nj < 4; ++nj) {
                                const unsigned* A = pass ? Al[mi] : Ah[mi];
                                unsigned b0 = Bf[nj >> 1][nj & 1];
                                unsigned b1 = Bf[nj >> 1][(nj & 1) + 2];
                                mma_f16(acc[mi][nj], A, b0, b1);
                            }
                    }
                }
                __syncwarp();
                if (lane == 0) MBARRIVE(empt[buf]);
            }

            // -------- fused epilogue (smem c, smem h stage) --------
            float oth[4][4];
#pragma unroll
            for (int nj = 0; nj < 4; ++nj)
#pragma unroll
                for (int k = 0; k < 4; ++k) {
                    float sendv = gsel ? acc[0][nj][k] : acc[1][nj][k];
                    oth[nj][k] = __shfl_xor_sync(0xFFFFFFFFu, sendv, 1);
                }

#pragma unroll
            for (int rh = 0; rh < 2; ++rh) {
                const int row = wm * 32 + gsel * 16 + rh * 8 + q;
                const int b = m0 + row;
                const int dd = ddv[rh];
#pragma unroll
                for (int nj = 0; nj < 4; ++nj) {
                    float own0 = gsel ? acc[1][nj][rh * 2 + 0] : acc[0][nj][rh * 2 + 0];
                    float own1 = gsel ? acc[1][nj][rh * 2 + 1] : acc[0][nj][rh * 2 + 1];
                    float o0 = oth[nj][rh * 2 + 0];
                    float o1 = oth[nj][rh * 2 + 1];
                    float zg = gsel ? o0 : own0;
                    float zi = gsel ? o1 : own1;
                    float zf = gsel ? own0 : o0;
                    float zo = gsel ? own1 : o1;

                    const int hcol = wn * 8 + nj * 2 + psel;
                    const int gxb = dd * 128 + hcol * 4;
                    zg += sh_gx[gxb + 0];
                    zi += sh_gx[gxb + 1];
                    zf += sh_gx[gxb + 2];
                    zo += sh_gx[gxb + 3];

                    const int cidx = row * 32 + hcol;
                    float cold = sh_c[cidx];
                    float cn = tanh_fast(zg) * sigf(zi) + cold * sigf(zf);
                    float hn = tanh_fast(cn) * sigf(zo);
                    sh_c[cidx] = cn;

                    __half hh = __float2half(hn);
                    __half hl = __float2half(hn - __half2float(hh));
                    unsigned so = sw64((unsigned)((row >> 3) * 512 + (row & 7) * 64 + hcol * 2));
                    *(__half*)(smem + SM_HHI + so) = hh;
                    *(__half*)(smem + SM_HLO + so) = hl;

                    if (t == Tlen - 1)
                        g_hfin[b * Hdim + nt * 32 + hcol] = hn;
                }
            }
        }

        __syncthreads();
        if (tid == 0) {
            // publish h slabs for next step
            FENCE_ASYNC();
            BULK_S2G((void*)g_hsw[np][0][mt][nt], sbase + SM_HHI, SLAB8);
            BULK_S2G((void*)g_hsw[np][1][mt][nt], sbase + SM_HLO, SLAB8);
            BULK_COMMIT();
            BULK_WAIT0();
            __threadfence();
            // row-scoped barrier: only the 16 CTAs sharing mt exchange A slabs
            unsigned s = lsense ^ 1u;
            if (atomicAdd(&g_rowbar[mt * 32], 1u) == (unsigned)(NT - 1)) {
                g_rowbar[mt * 32] = 0u;
                __threadfence();
                g_rowsense[mt * 32] = s;
            } else {
                while (g_rowsense[mt * 32] != s) { }
            }
            lsense = s;
        }
        __syncthreads();
    }
}

// ---------------- head: p = h @ Wp + bp; log_softmax ----------------
__global__ void lstm_head(const float* __restrict__ Wp,
                          const float* __restrict__ bp,
                          float* __restrict__ out) {
    int warp = threadIdx.x >> 5;
    int lane = threadIdx.x & 31;
    int row = blockIdx.x * 8 + warp;
    if (row >= Bsz) return;

    const float* __restrict__ h = &g_hfin[row * Hdim];
    float acc[NCLS];
#pragma unroll
    for (int n = 0; n < NCLS; ++n) acc[n] = 0.0f;
    for (int k = lane; k < Hdim; k += 32) {
        float hv = h[k];
#pragma unroll
        for (int n = 0; n < NCLS; ++n) acc[n] += hv * Wp[k * NCLS + n];
    }
#pragma unroll
    for (int off = 16; off > 0; off >>= 1)
#pragma unroll
        for (int n = 0; n < NCLS; ++n)
            acc[n] += __shfl_xor_sync(0xFFFFFFFFu, acc[n], off);

    if (lane == 0) {
        float p[NCLS], m = -1e30f;
#pragma unroll
        for (int n = 0; n < NCLS; ++n) { p[n] = acc[n] + bp[n]; m = fmaxf(m, p[n]); }
        float ssum = 0.0f;
#pragma unroll
        for (int n = 0; n < NCLS; ++n) ssum += expf(p[n] - m);
        float lse = m + logf(ssum);
#pragma unroll
        for (int n = 0; n < NCLS; ++n) out[row * NCLS + n] = p[n] - lse;
    }
}

extern "C" void kernel_launch(void* const* d_in, const int* in_sizes, int n_in,
                              void* d_out, int out_size) {
    const int*   x   = (const int*)  d_in[0];
    const float* emb = (const float*)d_in[1];
    const float* Wx  = (const float*)d_in[2];
    const float* Wh  = (const float*)d_in[3];
    const float* b   = (const float*)d_in[4];
    const float* Wp  = (const float*)d_in[5];
    const float* bp  = (const float*)d_in[6];
    float* out = (float*)d_out;

    cudaFuncSetAttribute(lstm_persist, cudaFuncAttributeMaxDynamicSharedMemorySize, SMEM_TOTAL);

    lstm_init<<<4096, 256>>>(emb, Wx, b, Wh);

    dim3 grid(NT, MT);   // 16 x 8 = 128 CTAs, 1 per SM -> co-resident
    lstm_persist<<<grid, 544, SMEM_TOTAL>>>(x);

    lstm_head<<<Bsz / 8, 256>>>(Wp, bp, out);
}

// round 9
// speedup vs baseline: 5.8698x; 1.5486x over previous
#include <cuda_runtime.h>
#include <cuda_fp16.h>
#include <math.h>

// ---------------- problem constants ----------------
#define Bsz   1024
#define Tlen  128
#define Hdim  512
#define NCLS  10

// ---------------- tiling ----------------
#define MT 8            // M tiles (1024/128)
#define NT 16           // N tiles (2048/128) in permuted gate space
#define CH 16           // K chunks (512/32)
#define SLAB8 8192      // 128 rows x 32 cols x 2B, SW64 slab

// ---------------- persistent device state (pre-swizzled) ----------------
__device__ __align__(1024) unsigned char g_Wsw[NT][CH][SLAB8];      // fp16 W, 2MB
__device__ __align__(1024) unsigned char g_hsw[2][MT][CH][SLAB8];   // [parity][mtile][chunk] 2MB (fp16)
__device__ float g_hfin[Bsz * Hdim];
__device__ float g_gxp[3][2048];     // permuted gate-bias table
__device__ unsigned g_rowbar[MT * 32];
__device__ volatile unsigned g_rowsense[MT * 32];

// ---------------- PTX helpers (sm_103 plain — NO tcgen05) ----------------
__device__ __forceinline__ unsigned smem_u32(const void* p) {
    unsigned r;
    asm("{ .reg .u64 t; cvta.to.shared.u64 t, %1; cvt.u32.u64 %0, t; }" : "=r"(r) : "l"(p));
    return r;
}
__device__ __forceinline__ void bulk_g2s(unsigned dst, const void* src, unsigned bytes, unsigned mbar) {
    asm volatile("cp.async.bulk.shared::cluster.global.mbarrier::complete_tx::bytes [%0], [%1], %2, [%3];"
        :: "r"(dst), "l"(src), "r"(bytes), "r"(mbar) : "memory");
}
#define BULK_S2G(g, s, n) asm volatile("cp.async.bulk.global.shared::cta.bulk_group [%0], [%1], %2;" :: "l"(g), "r"(s), "r"(n) : "memory")
#define BULK_COMMIT() asm volatile("cp.async.bulk.commit_group;" ::: "memory")
#define BULK_WAIT0()  asm volatile("cp.async.bulk.wait_group 0;" ::: "memory")
#define MBINIT(a, c)  asm volatile("mbarrier.init.shared.b64 [%0], %1;" :: "r"(a), "r"(c) : "memory")
#define MBEXPECT(a, n) asm volatile("mbarrier.arrive.expect_tx.shared.b64 _, [%0], %1;" :: "r"(a), "r"(n) : "memory")
#define MBARRIVE(a)   asm volatile("mbarrier.arrive.shared.b64 _, [%0];" :: "r"(a) : "memory")
#define FENCE_ASYNC() asm volatile("fence.proxy.async.shared::cta;" ::: "memory")

#define MBWAIT(mbar, parity) do {                                            \
    unsigned _m = (mbar); unsigned _p = (parity); unsigned _done;            \
    asm volatile("{\n\t.reg .pred p;\n\t"                                    \
        "mbarrier.try_wait.parity.acquire.cta.shared::cta.b64 p, [%1], %2;\n\t" \
        "selp.b32 %0, 1, 0, p;\n\t}"                                         \
        : "=r"(_done) : "r"(_m), "r"(_p) : "memory");                        \
    if (!_done) {                                                            \
        asm volatile("{\n\t.reg .pred P1;\n\t"                               \
            "WL_%=:\n\t"                                                     \
            "mbarrier.try_wait.parity.acquire.cta.shared::cta.b64 P1, [%0], %1, 0x989680;\n\t" \
            "@P1 bra.uni WD_%=;\n\t"                                         \
            "bra.uni WL_%=;\n\t"                                             \
            "WD_%=:\n\t}"                                                    \
            :: "r"(_m), "r"(_p) : "memory");                                 \
    }                                                                        \
} while (0)

__device__ __forceinline__ void ldsm4(unsigned* r, unsigned addr) {
    asm volatile("ldmatrix.sync.aligned.m8n8.x4.shared.b16 {%0,%1,%2,%3}, [%4];"
        : "=r"(r[0]), "=r"(r[1]), "=r"(r[2]), "=r"(r[3]) : "r"(addr));
}
__device__ __forceinline__ void mma_f16(float* d, const unsigned* a, unsigned b0, unsigned b1) {
    asm volatile("mma.sync.aligned.m16n8k16.row.col.f32.f16.f16.f32 "
        "{%0,%1,%2,%3}, {%4,%5,%6,%7}, {%8,%9}, {%0,%1,%2,%3};"
        : "+f"(d[0]), "+f"(d[1]), "+f"(d[2]), "+f"(d[3])
        : "r"(a[0]), "r"(a[1]), "r"(a[2]), "r"(a[3]), "r"(b0), "r"(b1));
}

__device__ __forceinline__ unsigned sw64(unsigned o) { return o ^ ((o >> 3) & 0x30); }
__device__ __forceinline__ float sigf(float x) { return __fdividef(1.0f, 1.0f + __expf(-x)); }
__device__ __forceinline__ float tanh_fast(float x) {
    float a = fabsf(x);
    float e = __expf(2.0f * a);
    float r = 1.0f - __fdividef(2.0f, e + 1.0f);   // inf-safe
    return copysignf(r, x);
}

// ---------------- init ----------------
__global__ void lstm_init(const float* __restrict__ emb,
                          const float* __restrict__ Wx,
                          const float* __restrict__ bias,
                          const float* __restrict__ Wh) {
    int i = blockIdx.x * blockDim.x + threadIdx.x;   // 0 .. 1M-1

    // Wsw: permuted c = hcol*4 + gate; SW64 slabs of 32 k-cols; single fp16
    {
        int c = i >> 9;              // 0..2047
        int k = i & 511;
        int r = (c & 3) * Hdim + (c >> 2);
        float w = Wh[r * Hdim + k];
        int ntile = c >> 7, rl = c & 127, chunk = k >> 5, col = k & 31;
        unsigned byte = (unsigned)((rl >> 3) * 512 + (rl & 7) * 64 + col * 2);
        unsigned so = sw64(byte);
        *(__half*)(g_Wsw[ntile][chunk] + so) = __float2half(w);
    }
    // zero h parity-0 slabs: 1MB = 256K words
    if (i < 262144) ((unsigned*)g_hsw[0])[i] = 0u;
    // gx table (permuted)
    if (i < 3 * 2048) {
        int d = i >> 11, c = i & 2047;
        int r = (c & 3) * Hdim + (c >> 2);
        g_gxp[d][c] = bias[r] + Wx[r * 2 + 0] * emb[d * 2 + 0]
                              + Wx[r * 2 + 1] * emb[d * 2 + 1];
    }
    if (i < MT * 32) { g_rowbar[i] = 0u; g_rowsense[i] = 0u; }
}

// ---------------- persistent LSTM ----------------
// smem: [0..64) full[4]+empty[4], [64] wbar, [128..1664) gx,
//       [2048..18432) c, [18432..26624) h stage, [34816..165888) W resident,
//       [165888..231424) 4x16KB A ring (2 chunks per slot)
#define SM_MB     0
#define SM_WBAR   64
#define SM_GX     128
#define SM_C      2048
#define SM_HHI    18432
#define SM_W      34816
#define SM_ABUF   165888
#define ABUFB     16384
#define NSLOT     8           // 8 slots/step, 2 chunks each
#define SMEM_TOTAL (SM_ABUF + 4 * ABUFB)   // 231424

__global__ __launch_bounds__(544, 1)
void lstm_persist(const int* __restrict__ x) {
    extern __shared__ char smem[];
    const unsigned sbase = smem_u32(smem);
    const int tid = threadIdx.x;
    const int nt = blockIdx.x, mt = blockIdx.y;
    const int m0 = mt * 128, n0 = nt * 128;

    float* sh_gx = (float*)(smem + SM_GX);
    float* sh_c  = (float*)(smem + SM_C);
    if (tid < 384) {
        int d = tid >> 7, c = tid & 127;
        sh_gx[d * 128 + c] = g_gxp[d][n0 + c];
    }
    for (int i = tid; i < 128 * 32; i += 544) sh_c[i] = 0.0f;

    unsigned full[4], empt[4];
#pragma unroll
    for (int i = 0; i < 4; ++i) { full[i] = sbase + SM_MB + i * 8; empt[i] = sbase + SM_MB + 32 + i * 8; }
    const unsigned wbar = sbase + SM_WBAR;
    if (tid == 0) {
#pragma unroll
        for (int i = 0; i < 4; ++i) { MBINIT(full[i], 1); MBINIT(empt[i], 16); }
        MBINIT(wbar, 1);
        FENCE_ASYNC();
    }
    __syncthreads();

    // one-time W residency load (128KB contiguous)
    if (tid == 0) {
        MBEXPECT(wbar, 16 * SLAB8);
        bulk_g2s(sbase + SM_W, g_Wsw[nt], 16 * SLAB8, wbar);
    }

    const int lane = tid & 31, wid = tid >> 5;

    // ---- compute-warp constants (valid for wid < 16) ----
    const int wm = wid >> 2, wn = wid & 3;
    unsigned aRow[2], bRowSw[2];
#pragma unroll
    for (int mi = 0; mi < 2; ++mi) {
        int r = wm * 32 + mi * 16 + (lane & 15);
        aRow[mi] = sw64((unsigned)((r >> 3) * 512 + (r & 7) * 64));
    }
#pragma unroll
    for (int ng = 0; ng < 2; ++ng) {
        int r = wn * 32 + ng * 16 + (lane & 15);
        // swizzled row offset kept SEPARATE: XOR with kb before adding base
        bRowSw[ng] = sw64((unsigned)((r >> 3) * 512 + (r & 7) * 64));
    }
    const unsigned wbase = sbase + SM_W;
    const unsigned colx = (unsigned)((lane >> 4) * 16);
    const int gsel = lane & 1;
    const int psel = (lane >> 1) & 1;
    const int q = lane >> 2;

    if (wid < 16) MBWAIT(wbar, 0);   // W resident before first B ldsm

    unsigned lsense = 0;

    for (int t = 0; t < Tlen; ++t) {
        const int par = t & 1, np = par ^ 1;

        if (wid == 16) {
            // -------- producer warp (lane 0 only): 8 slots x 16KB (2 chunks) --------
            if (lane == 0) {
                for (int sl = 0; sl < NSLOT; ++sl) {
                    int buf = sl & 3;
                    unsigned pe = ((sl >> 2) & 1) ^ 1;      // empty-wait parity
                    MBWAIT(empt[buf], pe);
                    unsigned d0 = sbase + SM_ABUF + buf * ABUFB;
                    MBEXPECT(full[buf], ABUFB);
                    bulk_g2s(d0, g_hsw[par][mt][2 * sl], ABUFB, full[buf]);  // chunks 2sl,2sl+1
                }
            }
        } else {
            // -------- x prefetch for this step --------
            int ddv[2];
#pragma unroll
            for (int rh = 0; rh < 2; ++rh) {
                int row = wm * 32 + gsel * 16 + rh * 8 + q;
                ddv[rh] = x[(m0 + row) * Tlen + t];
            }

            // -------- 16 compute warps: each 32(M) x 32(N), single fp16 pass --------
            float acc[2][4][4];
#pragma unroll
            for (int i = 0; i < 2; ++i)
#pragma unroll
                for (int j = 0; j < 4; ++j)
#pragma unroll
                    for (int k = 0; k < 4; ++k) acc[i][j][k] = 0.0f;

#pragma unroll 4
            for (int sl = 0; sl < NSLOT; ++sl) {
                int buf = sl & 3;
                unsigned pf = (sl >> 2) & 1;                // full-wait parity
                MBWAIT(full[buf], pf);
#pragma unroll
                for (int sub = 0; sub < 2; ++sub) {
                    const int ch = 2 * sl + sub;
                    unsigned aBase = sbase + SM_ABUF + buf * ABUFB + sub * SLAB8;
                    unsigned bB = wbase + (unsigned)(ch * SLAB8);
#pragma unroll
                    for (int kh = 0; kh < 2; ++kh) {
                        unsigned kb = (unsigned)(kh * 32) + colx;
                        unsigned Ah[2][4], Bf[2][4];
#pragma unroll
                        for (int mi = 0; mi < 2; ++mi)
                            ldsm4(Ah[mi], aBase + (aRow[mi] ^ kb));
#pragma unroll
                        for (int ng = 0; ng < 2; ++ng)
                            ldsm4(Bf[ng], bB + (bRowSw[ng] ^ kb));
#pragma unroll
                        for (int mi = 0; mi < 2; ++mi)
#pragma unroll
                            for (int nj = 0; nj < 4; ++nj) {
                                unsigned b0 = Bf[nj >> 1][nj & 1];
                                unsigned b1 = Bf[nj >> 1][(nj & 1) + 2];
                                mma_f16(acc[mi][nj], Ah[mi], b0, b1);
                            }
                    }
                }
                __syncwarp();
                if (lane == 0) MBARRIVE(empt[buf]);
            }

            // -------- fused epilogue (smem c, smem h stage) --------
            float oth[4][4];
#pragma unroll
            for (int nj = 0; nj < 4; ++nj)
#pragma unroll
                for (int k = 0; k < 4; ++k) {
                    float sendv = gsel ? acc[0][nj][k] : acc[1][nj][k];
                    oth[nj][k] = __shfl_xor_sync(0xFFFFFFFFu, sendv, 1);
                }

#pragma unroll
            for (int rh = 0; rh < 2; ++rh) {
                const int row = wm * 32 + gsel * 16 + rh * 8 + q;
                const int b = m0 + row;
                const int dd = ddv[rh];
#pragma unroll
                for (int nj = 0; nj < 4; ++nj) {
                    float own0 = gsel ? acc[1][nj][rh * 2 + 0] : acc[0][nj][rh * 2 + 0];
                    float own1 = gsel ? acc[1][nj][rh * 2 + 1] : acc[0][nj][rh * 2 + 1];
                    float o0 = oth[nj][rh * 2 + 0];
                    float o1 = oth[nj][rh * 2 + 1];
                    float zg = gsel ? o0 : own0;
                    float zi = gsel ? o1 : own1;
                    float zf = gsel ? own0 : o0;
                    float zo = gsel ? own1 : o1;

                    const int hcol = wn * 8 + nj * 2 + psel;
                    const int gxb = dd * 128 + hcol * 4;
                    zg += sh_gx[gxb + 0];
                    zi += sh_gx[gxb + 1];
                    zf += sh_gx[gxb + 2];
                    zo += sh_gx[gxb + 3];

                    const int cidx = row * 32 + hcol;
                    float cold = sh_c[cidx];
                    float cn = tanh_fast(zg) * sigf(zi) + cold * sigf(zf);
                    float hn = tanh_fast(cn) * sigf(zo);
                    sh_c[cidx] = cn;

                    unsigned so = sw64((unsigned)((row >> 3) * 512 + (row & 7) * 64 + hcol * 2));
                    *(__half*)(smem + SM_HHI + so) = __float2half(hn);

                    if (t == Tlen - 1)
                        g_hfin[b * Hdim + nt * 32 + hcol] = hn;
                }
            }
        }

        __syncthreads();
        if (tid == 0) {
            // publish h slab for next step (chunk nt of mtile mt)
            FENCE_ASYNC();
            BULK_S2G((void*)g_hsw[np][mt][nt], sbase + SM_HHI, SLAB8);
            BULK_COMMIT();
            BULK_WAIT0();
            __threadfence();
            // row-scoped barrier: only the 16 CTAs sharing mt exchange A slabs
            unsigned s = lsense ^ 1u;
            if (atomicAdd(&g_rowbar[mt * 32], 1u) == (unsigned)(NT - 1)) {
                g_rowbar[mt * 32] = 0u;
                __threadfence();
                g_rowsense[mt * 32] = s;
            } else {
                while (g_rowsense[mt * 32] != s) { }
            }
            lsense = s;
        }
        __syncthreads();
    }
}

// ---------------- head: p = h @ Wp + bp; log_softmax ----------------
__global__ void lstm_head(const float* __restrict__ Wp,
                          const float* __restrict__ bp,
                          float* __restrict__ out) {
    int warp = threadIdx.x >> 5;
    int lane = threadIdx.x & 31;
    int row = blockIdx.x * 8 + warp;
    if (row >= Bsz) return;

    const float* __restrict__ h = &g_hfin[row * Hdim];
    float acc[NCLS];
#pragma unroll
    for (int n = 0; n < NCLS; ++n) acc[n] = 0.0f;
    for (int k = lane; k < Hdim; k += 32) {
        float hv = h[k];
#pragma unroll
        for (int n = 0; n < NCLS; ++n) acc[n] += hv * Wp[k * NCLS + n];
    }
#pragma unroll
    for (int off = 16; off > 0; off >>= 1)
#pragma unroll
        for (int n = 0; n < NCLS; ++n)
            acc[n] += __shfl_xor_sync(0xFFFFFFFFu, acc[n], off);

    if (lane == 0) {
        float p[NCLS], m = -1e30f;
#pragma unroll
        for (int n = 0; n < NCLS; ++n) { p[n] = acc[n] + bp[n]; m = fmaxf(m, p[n]); }
        float ssum = 0.0f;
#pragma unroll
        for (int n = 0; n < NCLS; ++n) ssum += expf(p[n] - m);
        float lse = m + logf(ssum);
#pragma unroll
        for (int n = 0; n < NCLS; ++n) out[row * NCLS + n] = p[n] - lse;
    }
}

extern "C" void kernel_launch(void* const* d_in, const int* in_sizes, int n_in,
                              void* d_out, int out_size) {
    const int*   x   = (const int*)  d_in[0];
    const float* emb = (const float*)d_in[1];
    const float* Wx  = (const float*)d_in[2];
    const float* Wh  = (const float*)d_in[3];
    const float* b   = (const float*)d_in[4];
    const float* Wp  = (const float*)d_in[5];
    const float* bp  = (const float*)d_in[6];
    float* out = (float*)d_out;

    cudaFuncSetAttribute(lstm_persist, cudaFuncAttributeMaxDynamicSharedMemorySize, SMEM_TOTAL);

    lstm_init<<<4096, 256>>>(emb, Wx, b, Wh);

    dim3 grid(NT, MT);   // 16 x 8 = 128 CTAs, 1 per SM -> co-resident
    lstm_persist<<<grid, 544, SMEM_TOTAL>>>(x);

    lstm_head<<<Bsz / 8, 256>>>(Wp, bp, out);
}

// round 10
// speedup vs baseline: 5.9342x; 1.0110x over previous
#include <cuda_runtime.h>
#include <cuda_fp16.h>
#include <math.h>

// ---------------- problem constants ----------------
#define Bsz   1024
#define Tlen  128
#define Hdim  512
#define NCLS  10

// ---------------- tiling ----------------
#define MT 8            // M tiles (1024/128)
#define NT 16           // N tiles (2048/128) in permuted gate space
#define CH 16           // K chunks (512/32)
#define SLAB8 8192      // 128 rows x 32 cols x 2B, SW64 slab

// ---------------- persistent device state (pre-swizzled) ----------------
__device__ __align__(1024) unsigned char g_Wsw[NT][CH][SLAB8];      // fp16 W, 2MB
__device__ __align__(1024) unsigned char g_hsw[2][MT][CH][SLAB8];   // [parity][mtile][chunk] 2MB (fp16)
__device__ float g_hfin[Bsz * Hdim];
__device__ float g_gxp[3][2048];     // permuted gate-bias table
__device__ unsigned g_rowbar[MT * 32];
__device__ volatile unsigned g_rowsense[MT * 32];

// ---------------- PTX helpers (sm_103 plain — NO tcgen05) ----------------
__device__ __forceinline__ unsigned smem_u32(const void* p) {
    unsigned r;
    asm("{ .reg .u64 t; cvta.to.shared.u64 t, %1; cvt.u32.u64 %0, t; }" : "=r"(r) : "l"(p));
    return r;
}
__device__ __forceinline__ void bulk_g2s(unsigned dst, const void* src, unsigned bytes, unsigned mbar) {
    asm volatile("cp.async.bulk.shared::cluster.global.mbarrier::complete_tx::bytes [%0], [%1], %2, [%3];"
        :: "r"(dst), "l"(src), "r"(bytes), "r"(mbar) : "memory");
}
#define BULK_S2G(g, s, n) asm volatile("cp.async.bulk.global.shared::cta.bulk_group [%0], [%1], %2;" :: "l"(g), "r"(s), "r"(n) : "memory")
#define BULK_COMMIT() asm volatile("cp.async.bulk.commit_group;" ::: "memory")
#define BULK_WAIT0()  asm volatile("cp.async.bulk.wait_group 0;" ::: "memory")
#define MBINIT(a, c)  asm volatile("mbarrier.init.shared.b64 [%0], %1;" :: "r"(a), "r"(c) : "memory")
#define MBEXPECT(a, n) asm volatile("mbarrier.arrive.expect_tx.shared.b64 _, [%0], %1;" :: "r"(a), "r"(n) : "memory")
#define MBARRIVE(a)   asm volatile("mbarrier.arrive.shared.b64 _, [%0];" :: "r"(a) : "memory")
#define FENCE_ASYNC() asm volatile("fence.proxy.async.shared::cta;" ::: "memory")

#define MBWAIT(mbar, parity) do {                                            \
    unsigned _m = (mbar); unsigned _p = (parity); unsigned _done;            \
    asm volatile("{\n\t.reg .pred p;\n\t"                                    \
        "mbarrier.try_wait.parity.acquire.cta.shared::cta.b64 p, [%1], %2;\n\t" \
        "selp.b32 %0, 1, 0, p;\n\t}"                                         \
        : "=r"(_done) : "r"(_m), "r"(_p) : "memory");                        \
    if (!_done) {                                                            \
        asm volatile("{\n\t.reg .pred P1;\n\t"                               \
            "WL_%=:\n\t"                                                     \
            "mbarrier.try_wait.parity.acquire.cta.shared::cta.b64 P1, [%0], %1, 0x989680;\n\t" \
            "@P1 bra.uni WD_%=;\n\t"                                         \
            "bra.uni WL_%=;\n\t"                                             \
            "WD_%=:\n\t}"                                                    \
            :: "r"(_m), "r"(_p) : "memory");                                 \
    }                                                                        \
} while (0)

__device__ __forceinline__ void ldsm4(unsigned* r, unsigned addr) {
    asm volatile("ldmatrix.sync.aligned.m8n8.x4.shared.b16 {%0,%1,%2,%3}, [%4];"
        : "=r"(r[0]), "=r"(r[1]), "=r"(r[2]), "=r"(r[3]) : "r"(addr));
}
__device__ __forceinline__ void mma_f16(float* d, const unsigned* a, unsigned b0, unsigned b1) {
    asm volatile("mma.sync.aligned.m16n8k16.row.col.f32.f16.f16.f32 "
        "{%0,%1,%2,%3}, {%4,%5,%6,%7}, {%8,%9}, {%0,%1,%2,%3};"
        : "+f"(d[0]), "+f"(d[1]), "+f"(d[2]), "+f"(d[3])
        : "r"(a[0]), "r"(a[1]), "r"(a[2]), "r"(a[3]), "r"(b0), "r"(b1));
}

__device__ __forceinline__ unsigned sw64(unsigned o) { return o ^ ((o >> 3) & 0x30); }
// fast activations: tanh.approx.f32 (sm_75+ base ISA, abs err ~2^-10.66)
__device__ __forceinline__ float tanha(float x) {
    float y;
    asm("tanh.approx.f32 %0, %1;" : "=f"(y) : "f"(x));
    return y;
}
__device__ __forceinline__ float siga(float x) {   // sigmoid(x) = 0.5*tanh(x/2)+0.5
    return fmaf(0.5f, tanha(0.5f * x), 0.5f);
}

// ---------------- init ----------------
__global__ void lstm_init(const float* __restrict__ emb,
                          const float* __restrict__ Wx,
                          const float* __restrict__ bias,
                          const float* __restrict__ Wh) {
    int i = blockIdx.x * blockDim.x + threadIdx.x;   // 0 .. 1M-1

    // Wsw: permuted c = hcol*4 + gate; SW64 slabs of 32 k-cols; single fp16
    {
        int c = i >> 9;              // 0..2047
        int k = i & 511;
        int r = (c & 3) * Hdim + (c >> 2);
        float w = Wh[r * Hdim + k];
        int ntile = c >> 7, rl = c & 127, chunk = k >> 5, col = k & 31;
        unsigned byte = (unsigned)((rl >> 3) * 512 + (rl & 7) * 64 + col * 2);
        unsigned so = sw64(byte);
        *(__half*)(g_Wsw[ntile][chunk] + so) = __float2half(w);
    }
    // zero h parity-0 slabs: 1MB = 256K words
    if (i < 262144) ((unsigned*)g_hsw[0])[i] = 0u;
    // gx table (permuted)
    if (i < 3 * 2048) {
        int d = i >> 11, c = i & 2047;
        int r = (c & 3) * Hdim + (c >> 2);
        g_gxp[d][c] = bias[r] + Wx[r * 2 + 0] * emb[d * 2 + 0]
                              + Wx[r * 2 + 1] * emb[d * 2 + 1];
    }
    if (i < MT * 32) { g_rowbar[i] = 0u; g_rowsense[i] = 0u; }
}

// ---------------- persistent LSTM ----------------
// smem: [0..64) full[4]+empty[4], [64] wbar, [128..1664) gx,
//       [2048..18432) c, [18432..26624) h stage, [34816..165888) W resident,
//       [165888..231424) 4x16KB A ring (2 chunks per slot)
#define SM_MB     0
#define SM_WBAR   64
#define SM_GX     128
#define SM_C      2048
#define SM_HHI    18432
#define SM_W      34816
#define SM_ABUF   165888
#define ABUFB     16384
#define NSLOT     8           // 8 slots/step, 2 chunks each
#define SMEM_TOTAL (SM_ABUF + 4 * ABUFB)   // 231424

__global__ __launch_bounds__(544, 1)
void lstm_persist(const int* __restrict__ x) {
    extern __shared__ char smem[];
    const unsigned sbase = smem_u32(smem);
    const int tid = threadIdx.x;
    const int nt = blockIdx.x, mt = blockIdx.y;
    const int m0 = mt * 128, n0 = nt * 128;

    float* sh_gx = (float*)(smem + SM_GX);
    float* sh_c  = (float*)(smem + SM_C);
    if (tid < 384) {
        int d = tid >> 7, c = tid & 127;
        sh_gx[d * 128 + c] = g_gxp[d][n0 + c];
    }
    for (int i = tid; i < 128 * 32; i += 544) sh_c[i] = 0.0f;

    unsigned full[4], empt[4];
#pragma unroll
    for (int i = 0; i < 4; ++i) { full[i] = sbase + SM_MB + i * 8; empt[i] = sbase + SM_MB + 32 + i * 8; }
    const unsigned wbar = sbase + SM_WBAR;
    if (tid == 0) {
#pragma unroll
        for (int i = 0; i < 4; ++i) { MBINIT(full[i], 1); MBINIT(empt[i], 16); }
        MBINIT(wbar, 1);
        FENCE_ASYNC();
    }
    __syncthreads();

    // one-time W residency load (128KB contiguous)
    if (tid == 0) {
        MBEXPECT(wbar, 16 * SLAB8);
        bulk_g2s(sbase + SM_W, g_Wsw[nt], 16 * SLAB8, wbar);
    }

    const int lane = tid & 31, wid = tid >> 5;

    // ---- compute-warp constants (valid for wid < 16) ----
    const int wm = wid >> 2, wn = wid & 3;
    unsigned aRow[2], bRowSw[2];
#pragma unroll
    for (int mi = 0; mi < 2; ++mi) {
        int r = wm * 32 + mi * 16 + (lane & 15);
        aRow[mi] = sw64((unsigned)((r >> 3) * 512 + (r & 7) * 64));
    }
#pragma unroll
    for (int ng = 0; ng < 2; ++ng) {
        int r = wn * 32 + ng * 16 + (lane & 15);
        // swizzled row offset kept SEPARATE: XOR with kb before adding base
        bRowSw[ng] = sw64((unsigned)((r >> 3) * 512 + (r & 7) * 64));
    }
    const unsigned wbase = sbase + SM_W;
    const unsigned colx = (unsigned)((lane >> 4) * 16);
    const int gsel = lane & 1;
    const int psel = (lane >> 1) & 1;
    const int q = lane >> 2;

    if (wid < 16) MBWAIT(wbar, 0);   // W resident before first B ldsm

    unsigned lsense = 0;             // used by producer lane 0 only

    for (int t = 0; t < Tlen; ++t) {
        const int par = t & 1, np = par ^ 1;

        if (wid == 16) {
            // -------- producer warp (lane 0 only): 8 slots x 16KB (2 chunks) --------
            if (lane == 0) {
                for (int sl = 0; sl < NSLOT; ++sl) {
                    int buf = sl & 3;
                    unsigned pe = ((sl >> 2) & 1) ^ 1;      // empty-wait parity
                    MBWAIT(empt[buf], pe);
                    unsigned d0 = sbase + SM_ABUF + buf * ABUFB;
                    MBEXPECT(full[buf], ABUFB);
                    bulk_g2s(d0, g_hsw[par][mt][2 * sl], ABUFB, full[buf]);  // chunks 2sl,2sl+1
                }
            }
        } else {
            // -------- x prefetch for this step --------
            int ddv[2];
#pragma unroll
            for (int rh = 0; rh < 2; ++rh) {
                int row = wm * 32 + gsel * 16 + rh * 8 + q;
                ddv[rh] = x[(m0 + row) * Tlen + t];
            }

            // -------- 16 compute warps: each 32(M) x 32(N), single fp16 pass --------
            float acc[2][4][4];
#pragma unroll
            for (int i = 0; i < 2; ++i)
#pragma unroll
                for (int j = 0; j < 4; ++j)
#pragma unroll
                    for (int k = 0; k < 4; ++k) acc[i][j][k] = 0.0f;

#pragma unroll 4
            for (int sl = 0; sl < NSLOT; ++sl) {
                int buf = sl & 3;
                unsigned pf = (sl >> 2) & 1;                // full-wait parity
                MBWAIT(full[buf], pf);
#pragma unroll
                for (int sub = 0; sub < 2; ++sub) {
                    const int ch = 2 * sl + sub;
                    unsigned aBase = sbase + SM_ABUF + buf * ABUFB + sub * SLAB8;
                    unsigned bB = wbase + (unsigned)(ch * SLAB8);
#pragma unroll
                    for (int kh = 0; kh < 2; ++kh) {
                        unsigned kb = (unsigned)(kh * 32) + colx;
                        unsigned Ah[2][4], Bf[2][4];
#pragma unroll
                        for (int mi = 0; mi < 2; ++mi)
                            ldsm4(Ah[mi], aBase + (aRow[mi] ^ kb));
#pragma unroll
                        for (int ng = 0; ng < 2; ++ng)
                            ldsm4(Bf[ng], bB + (bRowSw[ng] ^ kb));
#pragma unroll
                        for (int mi = 0; mi < 2; ++mi)
#pragma unroll
                            for (int nj = 0; nj < 4; ++nj) {
                                unsigned b0 = Bf[nj >> 1][nj & 1];
                                unsigned b1 = Bf[nj >> 1][(nj & 1) + 2];
                                mma_f16(acc[mi][nj], Ah[mi], b0, b1);
                            }
                    }
                }
                __syncwarp();
                if (lane == 0) MBARRIVE(empt[buf]);
            }

            // -------- fused epilogue (tanh.approx; smem c, smem h stage) --------
            float oth[4][4];
#pragma unroll
            for (int nj = 0; nj < 4; ++nj)
#pragma unroll
                for (int k = 0; k < 4; ++k) {
                    float sendv = gsel ? acc[0][nj][k] : acc[1][nj][k];
                    oth[nj][k] = __shfl_xor_sync(0xFFFFFFFFu, sendv, 1);
                }

#pragma unroll
            for (int rh = 0; rh < 2; ++rh) {
                const int row = wm * 32 + gsel * 16 + rh * 8 + q;
                const int b = m0 + row;
                const int dd = ddv[rh];
#pragma unroll
                for (int nj = 0; nj < 4; ++nj) {
                    float own0 = gsel ? acc[1][nj][rh * 2 + 0] : acc[0][nj][rh * 2 + 0];
                    float own1 = gsel ? acc[1][nj][rh * 2 + 1] : acc[0][nj][rh * 2 + 1];
                    float o0 = oth[nj][rh * 2 + 0];
                    float o1 = oth[nj][rh * 2 + 1];
                    float zg = gsel ? o0 : own0;
                    float zi = gsel ? o1 : own1;
                    float zf = gsel ? own0 : o0;
                    float zo = gsel ? own1 : o1;

                    const int hcol = wn * 8 + nj * 2 + psel;
                    const int gxb = dd * 128 + hcol * 4;
                    zg += sh_gx[gxb + 0];
                    zi += sh_gx[gxb + 1];
                    zf += sh_gx[gxb + 2];
                    zo += sh_gx[gxb + 3];

                    const int cidx = row * 32 + hcol;
                    float cold = sh_c[cidx];
                    float cn = tanha(zg) * siga(zi) + cold * siga(zf);
                    float hn = tanha(cn) * siga(zo);
                    sh_c[cidx] = cn;

                    unsigned so = sw64((unsigned)((row >> 3) * 512 + (row & 7) * 64 + hcol * 2));
                    *(__half*)(smem + SM_HHI + so) = __float2half(hn);

                    if (t == Tlen - 1)
                        g_hfin[b * Hdim + nt * 32 + hcol] = hn;
                }
            }
        }

        // single sync: h stage complete. Publish + row barrier live in the
        // producer warp only; compute warps fall through to the next step and
        // block on full[0], which the producer fills after the barrier.
        __syncthreads();
        if (wid == 16 && lane == 0) {
            FENCE_ASYNC();
            BULK_S2G((void*)g_hsw[np][mt][nt], sbase + SM_HHI, SLAB8);
            BULK_COMMIT();
            BULK_WAIT0();
            __threadfence();
            unsigned s = lsense ^ 1u;
            if (atomicAdd(&g_rowbar[mt * 32], 1u) == (unsigned)(NT - 1)) {
                g_rowbar[mt * 32] = 0u;
                __threadfence();
                g_rowsense[mt * 32] = s;
            } else {
                while (g_rowsense[mt * 32] != s) { }
            }
            lsense = s;
        }
    }
}

// ---------------- head: p = h @ Wp + bp; log_softmax ----------------
__global__ void lstm_head(const float* __restrict__ Wp,
                          const float* __restrict__ bp,
                          float* __restrict__ out) {
    int warp = threadIdx.x >> 5;
    int lane = threadIdx.x & 31;
    int row = blockIdx.x * 8 + warp;
    if (row >= Bsz) return;

    const float* __restrict__ h = &g_hfin[row * Hdim];
    float acc[NCLS];
#pragma unroll
    for (int n = 0; n < NCLS; ++n) acc[n] = 0.0f;
    for (int k = lane; k < Hdim; k += 32) {
        float hv = h[k];
#pragma unroll
        for (int n = 0; n < NCLS; ++n) acc[n] += hv * Wp[k * NCLS + n];
    }
#pragma unroll
    for (int off = 16; off > 0; off >>= 1)
#pragma unroll
        for (int n = 0; n < NCLS; ++n)
            acc[n] += __shfl_xor_sync(0xFFFFFFFFu, acc[n], off);

    if (lane == 0) {
        float p[NCLS], m = -1e30f;
#pragma unroll
        for (int n = 0; n < NCLS; ++n) { p[n] = acc[n] + bp[n]; m = fmaxf(m, p[n]); }
        float ssum = 0.0f;
#pragma unroll
        for (int n = 0; n < NCLS; ++n) ssum += expf(p[n] - m);
        float lse = m + logf(ssum);
#pragma unroll
        for (int n = 0; n < NCLS; ++n) out[row * NCLS + n] = p[n] - lse;
    }
}

extern "C" void kernel_launch(void* const* d_in, const int* in_sizes, int n_in,
                              void* d_out, int out_size) {
    const int*   x   = (const int*)  d_in[0];
    const float* emb = (const float*)d_in[1];
    const float* Wx  = (const float*)d_in[2];
    const float* Wh  = (const float*)d_in[3];
    const float* b   = (const float*)d_in[4];
    const float* Wp  = (const float*)d_in[5];
    const float* bp  = (const float*)d_in[6];
    float* out = (float*)d_out;

    cudaFuncSetAttribute(lstm_persist, cudaFuncAttributeMaxDynamicSharedMemorySize, SMEM_TOTAL);

    lstm_init<<<4096, 256>>>(emb, Wx, b, Wh);

    dim3 grid(NT, MT);   // 16 x 8 = 128 CTAs, 1 per SM -> co-resident
    lstm_persist<<<grid, 544, SMEM_TOTAL>>>(x);

    lstm_head<<<Bsz / 8, 256>>>(Wp, bp, out);
}